// round 2
// baseline (speedup 1.0000x reference)
#include <cuda_runtime.h>

#define BATCH 32
#define T 4096
#define IN_DIM 256
#define MEM 256
#define HID 512
#define S 128
#define NB (T / S)          // 32 time blocks
#define USTRIDE (T + S)     // 4224, front zero-pad of S per batch

// Scratch (device globals: allocation-free at runtime)
__device__ float g_u[BATCH * USTRIDE + 256];                 // padded relu(x@Wu)
__device__ float g_m[(size_t)BATCH * T * MEM];               // 134 MB conv output

// ---------------------------------------------------------------------------
// Zero the padded u buffer (pads must be 0; body overwritten by k_u)
// ---------------------------------------------------------------------------
__global__ void k_zero_u() {
    int i = blockIdx.x * 256 + threadIdx.x;
    if (i < BATCH * USTRIDE + 256) g_u[i] = 0.0f;
}

// ---------------------------------------------------------------------------
// u[b,t] = relu( dot(x[b,t,:], W_u) )   — one warp per (b,t)
// ---------------------------------------------------------------------------
__global__ __launch_bounds__(256) void k_u(const float* __restrict__ x,
                                           const float* __restrict__ Wu) {
    __shared__ float w[IN_DIM];
    int tid = threadIdx.x;
    w[tid] = Wu[tid];   // blockDim = 256 = IN_DIM
    __syncthreads();

    int warp = tid >> 5, lane = tid & 31;
    int row = blockIdx.x * 8 + warp;          // row in [0, BATCH*T)
    const float* xr = x + (size_t)row * IN_DIM;

    float4 a = *(const float4*)(xr + lane * 4);
    float4 b = *(const float4*)(xr + 128 + lane * 4);
    int j0 = lane * 4;
    float s = a.x * w[j0] + a.y * w[j0 + 1] + a.z * w[j0 + 2] + a.w * w[j0 + 3]
            + b.x * w[128 + j0] + b.y * w[128 + j0 + 1]
            + b.z * w[128 + j0 + 2] + b.w * w[128 + j0 + 3];
#pragma unroll
    for (int off = 16; off; off >>= 1) s += __shfl_xor_sync(0xffffffffu, s, off);

    if (lane == 0) {
        int bb = row >> 12, t = row & (T - 1);
        g_u[bb * USTRIDE + S + t] = fmaxf(s, 0.0f);
    }
}

// ---------------------------------------------------------------------------
// Block-Toeplitz causal conv:
//   m[b, jb*S+tau, k] = sum_{l=0..jb} sum_{dl=0..S-1}
//                           u[b, (jb-l)*S + tau - dl] * H[k, l*S + dl]
// Tile: 128 tau x 64 k per block. Grid (jb=32, kslab=4, b=32).
// ---------------------------------------------------------------------------
__global__ __launch_bounds__(256) void k_conv(const float* __restrict__ H) {
    int jb = blockIdx.x, ks = blockIdx.y, b = blockIdx.z;
    __shared__ __align__(16) float uw[256];
    __shared__ __align__(16) float Hs[S * 68];   // [delta][k], stride 68 (16B-aligned rows)

    int tid = threadIdx.x;
    int tx = tid & 15;          // k groups: k_local = tx*4 + q
    int ty = tid >> 4;          // tau groups: tau = ty*8 + r
    int ty8 = ty * 8;

    float acc[8][4];
#pragma unroll
    for (int r = 0; r < 8; ++r)
#pragma unroll
        for (int q = 0; q < 4; ++q) acc[r][q] = 0.0f;

    for (int i = 0; i <= jb; ++i) {
        __syncthreads();
        // u window: u[b, i*S - 127 .. i*S + 128] (front pad makes negatives zero)
        uw[tid] = g_u[b * USTRIDE + 1 + i * S + tid];
        // H tile for lag-block l = jb - i : Hs[delta][k] = H[ks*64+k, l*S+delta]
        {
            int l = jb - i;
            int kk = tid >> 2, q = tid & 3;
            const float* hp = H + (size_t)(ks * 64 + kk) * T + l * S + q * 32;
#pragma unroll
            for (int mm = 0; mm < 32; mm += 4) {
                float4 v = *(const float4*)(hp + mm);
                Hs[(q * 32 + mm + 0) * 68 + kk] = v.x;
                Hs[(q * 32 + mm + 1) * 68 + kk] = v.y;
                Hs[(q * 32 + mm + 2) * 68 + kk] = v.z;
                Hs[(q * 32 + mm + 3) * 68 + kk] = v.w;
            }
        }
        __syncthreads();

#pragma unroll 2
        for (int d = 0; d < S; ++d) {
            float4 hv = *(const float4*)&Hs[d * 68 + tx * 4];
            float av[8];
#pragma unroll
            for (int r = 0; r < 8; ++r) av[r] = uw[127 + ty8 + r - d];
#pragma unroll
            for (int r = 0; r < 8; ++r) {
                acc[r][0] = fmaf(av[r], hv.x, acc[r][0]);
                acc[r][1] = fmaf(av[r], hv.y, acc[r][1]);
                acc[r][2] = fmaf(av[r], hv.z, acc[r][2]);
                acc[r][3] = fmaf(av[r], hv.w, acc[r][3]);
            }
        }
    }

    // write m tile
#pragma unroll
    for (int r = 0; r < 8; ++r) {
        float4 v = make_float4(acc[r][0], acc[r][1], acc[r][2], acc[r][3]);
        size_t row = (size_t)b * T + jb * S + ty8 + r;
        *(float4*)&g_m[row * MEM + ks * 64 + tx * 4] = v;
    }
}

// ---------------------------------------------------------------------------
// h = relu([m | x] @ W_h^T); h_n = h[:, T-1, :]
// Tile: 128 rows x 64 outputs, K-chunks of 32. Grid (o-tiles=8, row-tiles=1024).
// ---------------------------------------------------------------------------
__global__ __launch_bounds__(256) void k_gemm2(const float* __restrict__ x,
                                               const float* __restrict__ Wh,
                                               float* __restrict__ out) {
    int ob = blockIdx.x, tb = blockIdx.y;
    __shared__ __align__(16) float As[128 * 36];   // [row][c], stride 36
    __shared__ __align__(16) float Ws[32 * 68];    // [c][o],  stride 68

    int tid = threadIdx.x;
    int tx = tid & 15;    // o_local = tx*4 + q
    int ty = tid >> 4;    // row_local = ty*8 + r
    int ty8 = ty * 8;

    float acc[8][4];
#pragma unroll
    for (int r = 0; r < 8; ++r)
#pragma unroll
        for (int q = 0; q < 4; ++q) acc[r][q] = 0.0f;

    for (int c0 = 0; c0 < MEM + IN_DIM; c0 += 32) {
        __syncthreads();
        // load A tile (from m for c0<256, else from x)
        {
            const float* src = (c0 < MEM)
                ? (g_m + (size_t)tb * 128 * MEM + c0)
                : (x + (size_t)tb * 128 * IN_DIM + (c0 - MEM));
            int row = tid >> 1, half = tid & 1;
            const float* sp = src + (size_t)row * 256 + half * 16;
#pragma unroll
            for (int mm = 0; mm < 16; mm += 4) {
                float4 v = *(const float4*)(sp + mm);
                *(float4*)&As[row * 36 + half * 16 + mm] = v;
            }
        }
        // load W tile transposed: Ws[c][o] = Wh[ob*64+o, c0+c]
        {
            int o = tid & 63, cg = tid >> 6;  // cg in [0,4): c = cg*8 + cc
            const float* wp = Wh + (size_t)(ob * 64 + o) * (MEM + IN_DIM) + c0 + cg * 8;
            float4 v0 = *(const float4*)wp;
            float4 v1 = *(const float4*)(wp + 4);
            Ws[(cg * 8 + 0) * 68 + o] = v0.x;
            Ws[(cg * 8 + 1) * 68 + o] = v0.y;
            Ws[(cg * 8 + 2) * 68 + o] = v0.z;
            Ws[(cg * 8 + 3) * 68 + o] = v0.w;
            Ws[(cg * 8 + 4) * 68 + o] = v1.x;
            Ws[(cg * 8 + 5) * 68 + o] = v1.y;
            Ws[(cg * 8 + 6) * 68 + o] = v1.z;
            Ws[(cg * 8 + 7) * 68 + o] = v1.w;
        }
        __syncthreads();

#pragma unroll 2
        for (int c = 0; c < 32; ++c) {
            float4 wv = *(const float4*)&Ws[c * 68 + tx * 4];
            float av[8];
#pragma unroll
            for (int r = 0; r < 8; ++r) av[r] = As[(ty8 + r) * 36 + c];
#pragma unroll
            for (int r = 0; r < 8; ++r) {
                acc[r][0] = fmaf(av[r], wv.x, acc[r][0]);
                acc[r][1] = fmaf(av[r], wv.y, acc[r][1]);
                acc[r][2] = fmaf(av[r], wv.z, acc[r][2]);
                acc[r][3] = fmaf(av[r], wv.w, acc[r][3]);
            }
        }
    }

    const size_t HSIZE = (size_t)BATCH * T * HID;   // h elements; h_n follows
#pragma unroll
    for (int r = 0; r < 8; ++r) {
        float4 v = make_float4(fmaxf(acc[r][0], 0.f), fmaxf(acc[r][1], 0.f),
                               fmaxf(acc[r][2], 0.f), fmaxf(acc[r][3], 0.f));
        size_t rowg = (size_t)tb * 128 + ty8 + r;
        *(float4*)&out[rowg * HID + ob * 64 + tx * 4] = v;
        if ((rowg & (size_t)(T - 1)) == (size_t)(T - 1)) {
            size_t bb = rowg >> 12;
            *(float4*)&out[HSIZE + bb * HID + ob * 64 + tx * 4] = v;
        }
    }
}

// ---------------------------------------------------------------------------
extern "C" void kernel_launch(void* const* d_in, const int* in_sizes, int n_in,
                              void* d_out, int out_size) {
    const float* x  = (const float*)d_in[0];   // (32, 4096, 256)
    const float* Wu = (const float*)d_in[1];   // (1, 256)
    const float* Wh = (const float*)d_in[2];   // (512, 512)
    const float* H  = (const float*)d_in[3];   // (256, 4096)
    float* out = (float*)d_out;                // h (32,4096,512) then h_n (32,512)

    (void)in_sizes; (void)n_in; (void)out_size;

    k_zero_u<<<(BATCH * USTRIDE + 256 + 255) / 256, 256>>>();
    k_u<<<BATCH * T / 8, 256>>>(x, Wu);
    k_conv<<<dim3(NB, MEM / 64, BATCH), 256>>>(H);
    k_gemm2<<<dim3(HID / 64, BATCH * T / 128), 256>>>(x, Wh, out);
}

// round 4
// speedup vs baseline: 1.9863x; 1.9863x over previous
#include <cuda_runtime.h>
#include <cuda_bf16.h>
#include <cstdint>

#define BATCH 32
#define T 4096
#define IN_DIM 256
#define MEM 256
#define HID 512
#define S 128
#define NB 32
#define USTRIDE (T + S)
#define HPAIR (T / 2)          // pairs per H row
#define MPAIR (MEM / 2)        // 128
#define XPAIR (IN_DIM / 2)     // 128
#define WPAIR ((MEM + IN_DIM) / 2)  // 256

// ---------------- scratch (device globals) ----------------
__device__ float    g_u[BATCH * USTRIDE + 8];
__device__ unsigned g_up_hi[BATCH * USTRIDE + 8];   // (u[y], u[y-1]) bf16x2
__device__ unsigned g_up_lo[BATCH * USTRIDE + 8];
__device__ unsigned g_Hp_hi[MEM * HPAIR];           // (H[n,2j], H[n,2j+1])
__device__ unsigned g_Hp_lo[MEM * HPAIR];
__device__ unsigned g_Wp_hi[HID * WPAIR];
__device__ unsigned g_Wp_lo[HID * WPAIR];
__device__ unsigned g_xp_hi[(size_t)BATCH * T * XPAIR];
__device__ unsigned g_xp_lo[(size_t)BATCH * T * XPAIR];
__device__ unsigned g_mp_hi[(size_t)BATCH * T * MPAIR];
__device__ unsigned g_mp_lo[(size_t)BATCH * T * MPAIR];

// ---------------- helpers ----------------
__device__ __forceinline__ unsigned pack2(float a, float b) {
    __nv_bfloat162 t = __floats2bfloat162_rn(a, b);
    return *reinterpret_cast<unsigned*>(&t);
}
__device__ __forceinline__ float bf16rt(float v) {           // round-trip through bf16
    return __bfloat162float(__float2bfloat16(v));
}
// D += A(16x16) * B(16x8), bf16 in, fp32 accum
__device__ __forceinline__ void mma16816(float* c, const unsigned* a,
                                         unsigned b0, unsigned b1) {
    asm volatile(
        "mma.sync.aligned.m16n8k16.row.col.f32.bf16.bf16.f32 "
        "{%0,%1,%2,%3},{%4,%5,%6,%7},{%8,%9},{%0,%1,%2,%3};"
        : "+f"(c[0]), "+f"(c[1]), "+f"(c[2]), "+f"(c[3])
        : "r"(a[0]), "r"(a[1]), "r"(a[2]), "r"(a[3]), "r"(b0), "r"(b1));
}

// ---------------------------------------------------------------------------
__global__ void k_zero_u() {
    int i = blockIdx.x * 256 + threadIdx.x;
    if (i < BATCH * USTRIDE + 8) g_u[i] = 0.0f;
}

// u[b,t] = relu(dot(x[b,t,:], W_u)) — one warp per row
__global__ __launch_bounds__(256) void k_u(const float* __restrict__ x,
                                           const float* __restrict__ Wu) {
    __shared__ float w[IN_DIM];
    int tid = threadIdx.x;
    w[tid] = Wu[tid];
    __syncthreads();
    int warp = tid >> 5, lane = tid & 31;
    int row = blockIdx.x * 8 + warp;
    const float* xr = x + (size_t)row * IN_DIM;
    float4 a = *(const float4*)(xr + lane * 4);
    float4 b = *(const float4*)(xr + 128 + lane * 4);
    int j0 = lane * 4;
    float s = a.x * w[j0] + a.y * w[j0 + 1] + a.z * w[j0 + 2] + a.w * w[j0 + 3]
            + b.x * w[128 + j0] + b.y * w[128 + j0 + 1]
            + b.z * w[128 + j0 + 2] + b.w * w[128 + j0 + 3];
#pragma unroll
    for (int off = 16; off; off >>= 1) s += __shfl_xor_sync(0xffffffffu, s, off);
    if (lane == 0) {
        int bb = row >> 12, t = row & (T - 1);
        g_u[bb * USTRIDE + S + t] = fmaxf(s, 0.0f);
    }
}

// reversed pairs: up[y] = (u[y], u[y-1]) as bf16x2 hi + residual lo
__global__ void k_pack_u() {
    int y = blockIdx.x * 256 + threadIdx.x;
    if (y >= BATCH * USTRIDE) return;
    float v0 = g_u[y];
    float v1 = (y > 0) ? g_u[y - 1] : 0.0f;
    float h0 = bf16rt(v0), h1 = bf16rt(v1);
    g_up_hi[y] = pack2(h0, h1);
    g_up_lo[y] = pack2(v0 - h0, v1 - h1);
}

__global__ void k_prep_H(const float* __restrict__ H) {
    int p = blockIdx.x * 256 + threadIdx.x;
    if (p >= MEM * HPAIR) return;
    float v0 = H[2 * p], v1 = H[2 * p + 1];
    float h0 = bf16rt(v0), h1 = bf16rt(v1);
    g_Hp_hi[p] = pack2(h0, h1);
    g_Hp_lo[p] = pack2(v0 - h0, v1 - h1);
}

__global__ void k_prep_W(const float* __restrict__ Wh) {
    int p = blockIdx.x * 256 + threadIdx.x;
    if (p >= HID * WPAIR) return;
    float v0 = Wh[2 * p], v1 = Wh[2 * p + 1];
    float h0 = bf16rt(v0), h1 = bf16rt(v1);
    g_Wp_hi[p] = pack2(h0, h1);
    g_Wp_lo[p] = pack2(v0 - h0, v1 - h1);
}

__global__ void k_prep_X(const float* __restrict__ x) {
    size_t p = (size_t)blockIdx.x * 256 + threadIdx.x;
    if (p >= (size_t)BATCH * T * XPAIR) return;
    float v0 = x[2 * p], v1 = x[2 * p + 1];
    float h0 = bf16rt(v0), h1 = bf16rt(v1);
    g_xp_hi[p] = pack2(h0, h1);
    g_xp_lo[p] = pack2(v0 - h0, v1 - h1);
}

// ---------------------------------------------------------------------------
// Conv: per (jb, ks, b) CTA computes m[b, jb*128 .. +127, ks*128 .. +127]
// as sum over i of Toeplitz(u window) @ H(lag jb-i)^T via mma.sync, 3-term bf16.
// 8 warps: wm = wid&3 (rows wm*32), wn = wid>>2 (cols wn*64).
// ---------------------------------------------------------------------------
__global__ __launch_bounds__(256, 2) void k_conv_hmma() {
    extern __shared__ unsigned sm[];
    unsigned* Hs_hi = sm;                    // 128 rows * 68
    unsigned* Hs_lo = sm + 128 * 68;
    unsigned* uw_hi = sm + 2 * 128 * 68;     // 256 pairs
    unsigned* uw_lo = uw_hi + 256;

    int tid = threadIdx.x, lane = tid & 31, wid = tid >> 5;
    int g = lane >> 2, tig = lane & 3;
    int wm = wid & 3, wn = wid >> 2;
    int jb = NB - 1 - (int)blockIdx.x;       // heavy tiles first
    int ks = blockIdx.y, b = blockIdx.z;

    float acc[2][8][4];
#pragma unroll
    for (int mt = 0; mt < 2; ++mt)
#pragma unroll
        for (int nt = 0; nt < 8; ++nt)
#pragma unroll
            for (int q = 0; q < 4; ++q) acc[mt][nt][q] = 0.0f;

    const int W0b = b * USTRIDE + S;
    const int srow = tid >> 1, shalf = tid & 1;

    for (int i = 0; i <= jb; ++i) {
        int l = jb - i;
        __syncthreads();
        // stage H tile (rows n, 64 pairs) hi+lo — coalesced uint4
        {
            const uint4* sh = (const uint4*)&g_Hp_hi[(size_t)(ks * 128 + srow) * HPAIR + l * 64 + shalf * 32];
            const uint4* sl = (const uint4*)&g_Hp_lo[(size_t)(ks * 128 + srow) * HPAIR + l * 64 + shalf * 32];
            uint4* dh = (uint4*)&Hs_hi[srow * 68 + shalf * 32];
            uint4* dl = (uint4*)&Hs_lo[srow * 68 + shalf * 32];
#pragma unroll
            for (int q = 0; q < 8; ++q) { dh[q] = sh[q]; dl[q] = sl[q]; }
        }
        // stage u pair window [W0 - 128, W0 + 127]
        {
            int Wb = W0b + i * S - 128;
            uw_hi[tid] = g_up_hi[Wb + tid];
            uw_lo[tid] = g_up_lo[Wb + tid];
        }
        __syncthreads();

#pragma unroll
        for (int kk = 0; kk < 8; ++kk) {
            unsigned ah[2][4], al[2][4];
#pragma unroll
            for (int mt = 0; mt < 2; ++mt) {
                int base = 128 + wm * 32 + mt * 16 + g - kk * 16 - 2 * tig;
                ah[mt][0] = uw_hi[base];     al[mt][0] = uw_lo[base];
                ah[mt][1] = uw_hi[base + 8]; al[mt][1] = uw_lo[base + 8];
                ah[mt][2] = uw_hi[base - 8]; al[mt][2] = uw_lo[base - 8];
                ah[mt][3] = ah[mt][0];       al[mt][3] = al[mt][0];   // Toeplitz diagonal
            }
#pragma unroll
            for (int nt = 0; nt < 8; ++nt) {
                int nb = (wn * 64 + nt * 8 + g) * 68 + kk * 8 + tig;
                unsigned bh0 = Hs_hi[nb], bh1 = Hs_hi[nb + 4];
                unsigned bl0 = Hs_lo[nb], bl1 = Hs_lo[nb + 4];
#pragma unroll
                for (int mt = 0; mt < 2; ++mt) {
                    mma16816(acc[mt][nt], ah[mt], bh0, bh1);
                    mma16816(acc[mt][nt], al[mt], bh0, bh1);
                    mma16816(acc[mt][nt], ah[mt], bl0, bl1);
                }
            }
        }
    }

    // epilogue: split m into bf16 hi/lo pairs (pairs along k) for gemm2
#pragma unroll
    for (int mt = 0; mt < 2; ++mt) {
        size_t row0 = (size_t)b * T + (size_t)jb * S + wm * 32 + mt * 16 + g;
#pragma unroll
        for (int nt = 0; nt < 8; ++nt) {
            int p = ks * 64 + wn * 32 + nt * 4 + tig;
            float c0 = acc[mt][nt][0], c1 = acc[mt][nt][1];
            float c2 = acc[mt][nt][2], c3 = acc[mt][nt][3];
            float h0 = bf16rt(c0), h1 = bf16rt(c1), h2 = bf16rt(c2), h3 = bf16rt(c3);
            g_mp_hi[row0 * MPAIR + p]       = pack2(h0, h1);
            g_mp_lo[row0 * MPAIR + p]       = pack2(c0 - h0, c1 - h1);
            g_mp_hi[(row0 + 8) * MPAIR + p] = pack2(h2, h3);
            g_mp_lo[(row0 + 8) * MPAIR + p] = pack2(c2 - h2, c3 - h3);
        }
    }
}

// ---------------------------------------------------------------------------
// h = relu([m|x] @ W_h^T): CTA = 128 rows x 128 outs, K=512 in 4 chunks of 128.
// ---------------------------------------------------------------------------
__global__ __launch_bounds__(256, 2) void k_gemm2_hmma(float* __restrict__ out) {
    extern __shared__ unsigned sm[];
    unsigned* As_hi = sm;                    // 128 * 68
    unsigned* As_lo = sm + 8704;
    unsigned* Ws_hi = sm + 17408;
    unsigned* Ws_lo = sm + 26112;

    int tid = threadIdx.x, lane = tid & 31, wid = tid >> 5;
    int g = lane >> 2, tig = lane & 3;
    int wm = wid & 3, wn = wid >> 2;
    int ob = blockIdx.x, tb = blockIdx.y;

    float acc[2][8][4];
#pragma unroll
    for (int mt = 0; mt < 2; ++mt)
#pragma unroll
        for (int nt = 0; nt < 8; ++nt)
#pragma unroll
            for (int q = 0; q < 4; ++q) acc[mt][nt][q] = 0.0f;

    const int srow = tid >> 1, shalf = tid & 1;

    for (int ch = 0; ch < 4; ++ch) {
        __syncthreads();
        // stage A chunk: m pairs for ch 0/1, x pairs for ch 2/3
        {
            size_t rowg = (size_t)tb * 128 + srow;
            const unsigned* ph;
            const unsigned* pl;
            if (ch < 2) {
                ph = &g_mp_hi[rowg * MPAIR + ch * 64 + shalf * 32];
                pl = &g_mp_lo[rowg * MPAIR + ch * 64 + shalf * 32];
            } else {
                ph = &g_xp_hi[rowg * XPAIR + (ch - 2) * 64 + shalf * 32];
                pl = &g_xp_lo[rowg * XPAIR + (ch - 2) * 64 + shalf * 32];
            }
            uint4* dh = (uint4*)&As_hi[srow * 68 + shalf * 32];
            uint4* dl = (uint4*)&As_lo[srow * 68 + shalf * 32];
#pragma unroll
            for (int q = 0; q < 8; ++q) { dh[q] = ((const uint4*)ph)[q]; dl[q] = ((const uint4*)pl)[q]; }
        }
        // stage W chunk
        {
            const uint4* sh = (const uint4*)&g_Wp_hi[(size_t)(ob * 128 + srow) * WPAIR + ch * 64 + shalf * 32];
            const uint4* sl = (const uint4*)&g_Wp_lo[(size_t)(ob * 128 + srow) * WPAIR + ch * 64 + shalf * 32];
            uint4* dh = (uint4*)&Ws_hi[srow * 68 + shalf * 32];
            uint4* dl = (uint4*)&Ws_lo[srow * 68 + shalf * 32];
#pragma unroll
            for (int q = 0; q < 8; ++q) { dh[q] = sh[q]; dl[q] = sl[q]; }
        }
        __syncthreads();

#pragma unroll
        for (int kk = 0; kk < 8; ++kk) {
            unsigned ah[2][4], al[2][4];
#pragma unroll
            for (int mt = 0; mt < 2; ++mt) {
                int base = (wm * 32 + mt * 16 + g) * 68 + kk * 8 + tig;
                ah[mt][0] = As_hi[base];           al[mt][0] = As_lo[base];
                ah[mt][1] = As_hi[base + 8 * 68];  al[mt][1] = As_lo[base + 8 * 68];
                ah[mt][2] = As_hi[base + 4];       al[mt][2] = As_lo[base + 4];
                ah[mt][3] = As_hi[base + 8 * 68 + 4]; al[mt][3] = As_lo[base + 8 * 68 + 4];
            }
#pragma unroll
            for (int nt = 0; nt < 8; ++nt) {
                int nb = (wn * 64 + nt * 8 + g) * 68 + kk * 8 + tig;
                unsigned bh0 = Ws_hi[nb], bh1 = Ws_hi[nb + 4];
                unsigned bl0 = Ws_lo[nb], bl1 = Ws_lo[nb + 4];
#pragma unroll
                for (int mt = 0; mt < 2; ++mt) {
                    mma16816(acc[mt][nt], ah[mt], bh0, bh1);
                    mma16816(acc[mt][nt], al[mt], bh0, bh1);
                    mma16816(acc[mt][nt], ah[mt], bl0, bl1);
                }
            }
        }
    }

    // epilogue: relu, write h and h_n
    const size_t HSIZE = (size_t)BATCH * T * HID;
#pragma unroll
    for (int mt = 0; mt < 2; ++mt) {
        size_t row0 = (size_t)tb * 128 + wm * 32 + mt * 16 + g;
#pragma unroll
        for (int nt = 0; nt < 8; ++nt) {
            int col = ob * 128 + wn * 64 + nt * 8 + tig * 2;
            float2 v0 = make_float2(fmaxf(acc[mt][nt][0], 0.f), fmaxf(acc[mt][nt][1], 0.f));
            float2 v1 = make_float2(fmaxf(acc[mt][nt][2], 0.f), fmaxf(acc[mt][nt][3], 0.f));
            *(float2*)&out[row0 * HID + col] = v0;
            *(float2*)&out[(row0 + 8) * HID + col] = v1;
            if ((row0 & (size_t)(T - 1)) == (size_t)(T - 1))
                *(float2*)&out[HSIZE + (row0 >> 12) * HID + col] = v0;
            if (((row0 + 8) & (size_t)(T - 1)) == (size_t)(T - 1))
                *(float2*)&out[HSIZE + ((row0 + 8) >> 12) * HID + col] = v1;
        }
    }
}

// ---------------------------------------------------------------------------
extern "C" void kernel_launch(void* const* d_in, const int* in_sizes, int n_in,
                              void* d_out, int out_size) {
    const float* x  = (const float*)d_in[0];   // (32, 4096, 256)
    const float* Wu = (const float*)d_in[1];   // (1, 256)
    const float* Wh = (const float*)d_in[2];   // (512, 512)
    const float* H  = (const float*)d_in[3];   // (256, 4096)
    float* out = (float*)d_out;

    (void)in_sizes; (void)n_in; (void)out_size;

    static int smem_set = 0;
    if (!smem_set) {
        cudaFuncSetAttribute(k_conv_hmma, cudaFuncAttributeMaxDynamicSharedMemorySize, 71680);
        cudaFuncSetAttribute(k_gemm2_hmma, cudaFuncAttributeMaxDynamicSharedMemorySize, 139264);
        smem_set = 1;
    }

    k_zero_u<<<(BATCH * USTRIDE + 8 + 255) / 256, 256>>>();
    k_u<<<BATCH * T / 8, 256>>>(x, Wu);
    k_pack_u<<<(BATCH * USTRIDE + 255) / 256, 256>>>();
    k_prep_H<<<(MEM * HPAIR + 255) / 256, 256>>>(H);
    k_prep_W<<<(HID * WPAIR + 255) / 256, 256>>>(Wh);
    k_prep_X<<<(int)(((size_t)BATCH * T * XPAIR + 255) / 256), 256>>>(x);
    k_conv_hmma<<<dim3(NB, 2, BATCH), 256, 71680>>>();
    k_gemm2_hmma<<<dim3(HID / 128, BATCH * T / 128), 256, 139264>>>(out);
}

// round 5
// speedup vs baseline: 2.2915x; 1.1537x over previous
#include <cuda_runtime.h>
#include <cuda_bf16.h>
#include <cstdint>

#define BATCH 32
#define T 4096
#define IN_DIM 256
#define MEM 256
#define HID 512
#define S 128
#define NB 32
#define USTRIDE (T + S)
#define HPAIR (T / 2)               // 2048 pairs per H row
#define MPAIR (MEM / 2)             // 128
#define XPAIR (IN_DIM / 2)          // 128
#define WPAIR ((MEM + IN_DIM) / 2)  // 256

// ---------------- scratch (device globals, 16B aligned for cp.async) --------
__device__ __align__(16) float    g_u[BATCH * USTRIDE + 8];
__device__ __align__(16) unsigned g_up_hi[BATCH * USTRIDE + 8];
__device__ __align__(16) unsigned g_up_lo[BATCH * USTRIDE + 8];
__device__ __align__(16) unsigned g_Hp_hi[MEM * HPAIR];
__device__ __align__(16) unsigned g_Hp_lo[MEM * HPAIR];
__device__ __align__(16) unsigned g_Wp_hi[HID * WPAIR];
__device__ __align__(16) unsigned g_Wp_lo[HID * WPAIR];
__device__ __align__(16) unsigned g_xp_hi[(size_t)BATCH * T * XPAIR];
__device__ __align__(16) unsigned g_xp_lo[(size_t)BATCH * T * XPAIR];
__device__ __align__(16) unsigned g_mp_hi[(size_t)BATCH * T * MPAIR];
__device__ __align__(16) unsigned g_mp_lo[(size_t)BATCH * T * MPAIR];

// ---------------- helpers ----------------
__device__ __forceinline__ unsigned pack2(float a, float b) {
    __nv_bfloat162 t = __floats2bfloat162_rn(a, b);
    return *reinterpret_cast<unsigned*>(&t);
}
__device__ __forceinline__ float bf16rt(float v) {
    return __bfloat162float(__float2bfloat16(v));
}
__device__ __forceinline__ uint32_t smem_u32(const void* p) {
    uint32_t a;
    asm("{ .reg .u64 t; cvta.to.shared.u64 t, %1; cvt.u32.u64 %0, t; }" : "=r"(a) : "l"(p));
    return a;
}
__device__ __forceinline__ void cp16(uint32_t saddr, const void* g) {
    asm volatile("cp.async.cg.shared.global [%0], [%1], 16;" :: "r"(saddr), "l"(g));
}
__device__ __forceinline__ void cp_commit() {
    asm volatile("cp.async.commit_group;" ::: "memory");
}
__device__ __forceinline__ void cp_wait1() {
    asm volatile("cp.async.wait_group 1;" ::: "memory");
}
__device__ __forceinline__ void cp_wait0() {
    asm volatile("cp.async.wait_group 0;" ::: "memory");
}
// D += A(16x16) * B(16x8), bf16 in, fp32 accum
__device__ __forceinline__ void mma16816(float* c, const unsigned* a,
                                         unsigned b0, unsigned b1) {
    asm volatile(
        "mma.sync.aligned.m16n8k16.row.col.f32.bf16.bf16.f32 "
        "{%0,%1,%2,%3},{%4,%5,%6,%7},{%8,%9},{%0,%1,%2,%3};"
        : "+f"(c[0]), "+f"(c[1]), "+f"(c[2]), "+f"(c[3])
        : "r"(a[0]), "r"(a[1]), "r"(a[2]), "r"(a[3]), "r"(b0), "r"(b1));
}

// ---------------------------------------------------------------------------
__global__ void k_zero_u() {
    int i = blockIdx.x * 256 + threadIdx.x;
    if (i < BATCH * USTRIDE + 8) g_u[i] = 0.0f;
}

__global__ __launch_bounds__(256) void k_u(const float* __restrict__ x,
                                           const float* __restrict__ Wu) {
    __shared__ float w[IN_DIM];
    int tid = threadIdx.x;
    w[tid] = Wu[tid];
    __syncthreads();
    int warp = tid >> 5, lane = tid & 31;
    int row = blockIdx.x * 8 + warp;
    const float* xr = x + (size_t)row * IN_DIM;
    float4 a = *(const float4*)(xr + lane * 4);
    float4 b = *(const float4*)(xr + 128 + lane * 4);
    int j0 = lane * 4;
    float s = a.x * w[j0] + a.y * w[j0 + 1] + a.z * w[j0 + 2] + a.w * w[j0 + 3]
            + b.x * w[128 + j0] + b.y * w[128 + j0 + 1]
            + b.z * w[128 + j0 + 2] + b.w * w[128 + j0 + 3];
#pragma unroll
    for (int off = 16; off; off >>= 1) s += __shfl_xor_sync(0xffffffffu, s, off);
    if (lane == 0) {
        int bb = row >> 12, t = row & (T - 1);
        g_u[bb * USTRIDE + S + t] = fmaxf(s, 0.0f);
    }
}

__global__ void k_pack_u() {
    int y = blockIdx.x * 256 + threadIdx.x;
    if (y >= BATCH * USTRIDE) return;
    float v0 = g_u[y];
    float v1 = (y > 0) ? g_u[y - 1] : 0.0f;
    float h0 = bf16rt(v0), h1 = bf16rt(v1);
    g_up_hi[y] = pack2(h0, h1);
    g_up_lo[y] = pack2(v0 - h0, v1 - h1);
}

__global__ void k_prep_H(const float* __restrict__ H) {
    int p = blockIdx.x * 256 + threadIdx.x;
    if (p >= MEM * HPAIR) return;
    float v0 = H[2 * p], v1 = H[2 * p + 1];
    float h0 = bf16rt(v0), h1 = bf16rt(v1);
    g_Hp_hi[p] = pack2(h0, h1);
    g_Hp_lo[p] = pack2(v0 - h0, v1 - h1);
}

__global__ void k_prep_W(const float* __restrict__ Wh) {
    int p = blockIdx.x * 256 + threadIdx.x;
    if (p >= HID * WPAIR) return;
    float v0 = Wh[2 * p], v1 = Wh[2 * p + 1];
    float h0 = bf16rt(v0), h1 = bf16rt(v1);
    g_Wp_hi[p] = pack2(h0, h1);
    g_Wp_lo[p] = pack2(v0 - h0, v1 - h1);
}

__global__ void k_prep_X(const float* __restrict__ x) {
    size_t p = (size_t)blockIdx.x * 256 + threadIdx.x;
    if (p >= (size_t)BATCH * T * XPAIR) return;
    float v0 = x[2 * p], v1 = x[2 * p + 1];
    float h0 = bf16rt(v0), h1 = bf16rt(v1);
    g_xp_hi[p] = pack2(h0, h1);
    g_xp_lo[p] = pack2(v0 - h0, v1 - h1);
}

// ---------------------------------------------------------------------------
// Conv: per (jb, ks, b) CTA: m tile 128 tau x 128 k, double-buffered cp.async.
// SMEM words: Hbuf[2] of (hi 8704 | lo 8704), then u[2] of (hi 256 | lo 256).
// ---------------------------------------------------------------------------
#define CV_HW 8704
#define CV_BUF 17408
#define CV_UW0 34816
#define CV_SMEM_BYTES ((CV_UW0 + 2 * 512) * 4)   // 143360

__global__ __launch_bounds__(256) void k_conv_hmma() {
    extern __shared__ unsigned sm[];
    uint32_t sb = smem_u32(sm);

    int tid = threadIdx.x, lane = tid & 31, wid = tid >> 5;
    int g = lane >> 2, tig = lane & 3;
    int wm = wid & 3, wn = wid >> 2;
    int jb = NB - 1 - (int)blockIdx.x;
    int ks = blockIdx.y, b = blockIdx.z;

    float acc[2][8][4];
#pragma unroll
    for (int mt = 0; mt < 2; ++mt)
#pragma unroll
        for (int nt = 0; nt < 8; ++nt)
#pragma unroll
            for (int q = 0; q < 4; ++q) acc[mt][nt][q] = 0.0f;

    const int srow = tid >> 1, shalf = tid & 1;
    const size_t hrow = (size_t)(ks * 128 + srow) * HPAIR + shalf * 32;

    auto stage = [&](int i, int p) {
        int l = jb - i;
        const unsigned* shh = &g_Hp_hi[hrow + l * 64];
        const unsigned* shl = &g_Hp_lo[hrow + l * 64];
        uint32_t dh = sb + (uint32_t)(p * CV_BUF + srow * 68 + shalf * 32) * 4;
        uint32_t dl = dh + CV_HW * 4;
#pragma unroll
        for (int q = 0; q < 8; ++q) {
            cp16(dh + q * 16, shh + q * 4);
            cp16(dl + q * 16, shl + q * 4);
        }
        int Wb = b * USTRIDE + i * S;   // window start (pairs), front pad covers t<0
        if (tid < 64)
            cp16(sb + (uint32_t)(CV_UW0 + p * 512 + tid * 4) * 4, &g_up_hi[Wb + tid * 4]);
        else if (tid < 128) {
            int t2 = tid - 64;
            cp16(sb + (uint32_t)(CV_UW0 + p * 512 + 256 + t2 * 4) * 4, &g_up_lo[Wb + t2 * 4]);
        }
        cp_commit();
    };

    stage(0, 0);
    for (int i = 0; i <= jb; ++i) {
        int p = i & 1;
        if (i < jb) { stage(i + 1, p ^ 1); cp_wait1(); }
        else        { cp_wait0(); }
        __syncthreads();

        unsigned* Hs_hi = sm + p * CV_BUF;
        unsigned* Hs_lo = Hs_hi + CV_HW;
        unsigned* uw_hi = sm + CV_UW0 + p * 512;
        unsigned* uw_lo = uw_hi + 256;

#pragma unroll
        for (int kk = 0; kk < 8; ++kk) {
            unsigned ah[2][4], al[2][4];
#pragma unroll
            for (int mt = 0; mt < 2; ++mt) {
                int base = 128 + wm * 32 + mt * 16 + g - kk * 16 - 2 * tig;
                ah[mt][0] = uw_hi[base];     al[mt][0] = uw_lo[base];
                ah[mt][1] = uw_hi[base + 8]; al[mt][1] = uw_lo[base + 8];
                ah[mt][2] = uw_hi[base - 8]; al[mt][2] = uw_lo[base - 8];
                ah[mt][3] = ah[mt][0];       al[mt][3] = al[mt][0];   // Toeplitz diag
            }
#pragma unroll
            for (int nt = 0; nt < 8; ++nt) {
                int nb = (wn * 64 + nt * 8 + g) * 68 + kk * 8 + tig;
                unsigned bh0 = Hs_hi[nb], bh1 = Hs_hi[nb + 4];
                unsigned bl0 = Hs_lo[nb], bl1 = Hs_lo[nb + 4];
#pragma unroll
                for (int mt = 0; mt < 2; ++mt) {
                    mma16816(acc[mt][nt], ah[mt], bh0, bh1);
                    mma16816(acc[mt][nt], al[mt], bh0, bh1);
                    mma16816(acc[mt][nt], ah[mt], bl0, bl1);
                }
            }
        }
        __syncthreads();
    }

    // epilogue: split m into bf16 hi/lo pairs for gemm2
#pragma unroll
    for (int mt = 0; mt < 2; ++mt) {
        size_t row0 = (size_t)b * T + (size_t)jb * S + wm * 32 + mt * 16 + g;
#pragma unroll
        for (int nt = 0; nt < 8; ++nt) {
            int p = ks * 64 + wn * 32 + nt * 4 + tig;
            float c0 = acc[mt][nt][0], c1 = acc[mt][nt][1];
            float c2 = acc[mt][nt][2], c3 = acc[mt][nt][3];
            float h0 = bf16rt(c0), h1 = bf16rt(c1), h2 = bf16rt(c2), h3 = bf16rt(c3);
            g_mp_hi[row0 * MPAIR + p]       = pack2(h0, h1);
            g_mp_lo[row0 * MPAIR + p]       = pack2(c0 - h0, c1 - h1);
            g_mp_hi[(row0 + 8) * MPAIR + p] = pack2(h2, h3);
            g_mp_lo[(row0 + 8) * MPAIR + p] = pack2(c2 - h2, c3 - h3);
        }
    }
}

// ---------------------------------------------------------------------------
// GEMM2: h = relu([m|x] @ W_h^T). CTA = 128 rows x 128 outs, 8 K-chunks of 64,
// double-buffered cp.async. SMEM per buf: As_hi|As_lo|Ws_hi|Ws_lo, 4608 words each.
// ---------------------------------------------------------------------------
#define G2_AS 4608
#define G2_BUF 18432
#define G2_SMEM_BYTES (2 * G2_BUF * 4)   // 147456

__global__ __launch_bounds__(256) void k_gemm2_hmma(float* __restrict__ out) {
    extern __shared__ unsigned sm[];
    uint32_t sb = smem_u32(sm);

    int tid = threadIdx.x, lane = tid & 31, wid = tid >> 5;
    int g = lane >> 2, tig = lane & 3;
    int wm = wid & 3, wn = wid >> 2;
    int ob = blockIdx.x, tb = blockIdx.y;

    float acc[2][8][4];
#pragma unroll
    for (int mt = 0; mt < 2; ++mt)
#pragma unroll
        for (int nt = 0; nt < 8; ++nt)
#pragma unroll
            for (int q = 0; q < 4; ++q) acc[mt][nt][q] = 0.0f;

    const int srow = tid >> 1, shalf = tid & 1;
    const size_t arow = ((size_t)tb * 128 + srow) * 128 + shalf * 16;
    const size_t wrow = (size_t)(ob * 128 + srow) * WPAIR + shalf * 16;

    auto stage = [&](int c, int p) {
        const unsigned *pah, *pal;
        if (c < 4) { pah = &g_mp_hi[arow + c * 32]; pal = &g_mp_lo[arow + c * 32]; }
        else       { pah = &g_xp_hi[arow + (c - 4) * 32]; pal = &g_xp_lo[arow + (c - 4) * 32]; }
        const unsigned* pwh = &g_Wp_hi[wrow + c * 32];
        const unsigned* pwl = &g_Wp_lo[wrow + c * 32];
        uint32_t d0 = sb + (uint32_t)(p * G2_BUF + srow * 36 + shalf * 16) * 4;
#pragma unroll
        for (int q = 0; q < 4; ++q) {
            cp16(d0 + q * 16,                  pah + q * 4);
            cp16(d0 + G2_AS * 4 + q * 16,      pal + q * 4);
            cp16(d0 + 2 * G2_AS * 4 + q * 16,  pwh + q * 4);
            cp16(d0 + 3 * G2_AS * 4 + q * 16,  pwl + q * 4);
        }
        cp_commit();
    };

    stage(0, 0);
    for (int c = 0; c < 8; ++c) {
        int p = c & 1;
        if (c < 7) { stage(c + 1, p ^ 1); cp_wait1(); }
        else       { cp_wait0(); }
        __syncthreads();

        unsigned* As_hi = sm + p * G2_BUF;
        unsigned* As_lo = As_hi + G2_AS;
        unsigned* Ws_hi = As_lo + G2_AS;
        unsigned* Ws_lo = Ws_hi + G2_AS;

#pragma unroll
        for (int kk = 0; kk < 4; ++kk) {
            unsigned ah[2][4], al[2][4];
#pragma unroll
            for (int mt = 0; mt < 2; ++mt) {
                int base = (wm * 32 + mt * 16 + g) * 36 + kk * 8 + tig;
                ah[mt][0] = As_hi[base];              al[mt][0] = As_lo[base];
                ah[mt][1] = As_hi[base + 8 * 36];     al[mt][1] = As_lo[base + 8 * 36];
                ah[mt][2] = As_hi[base + 4];          al[mt][2] = As_lo[base + 4];
                ah[mt][3] = As_hi[base + 8 * 36 + 4]; al[mt][3] = As_lo[base + 8 * 36 + 4];
            }
#pragma unroll
            for (int nt = 0; nt < 8; ++nt) {
                int nb = (wn * 64 + nt * 8 + g) * 36 + kk * 8 + tig;
                unsigned bh0 = Ws_hi[nb], bh1 = Ws_hi[nb + 4];
                unsigned bl0 = Ws_lo[nb], bl1 = Ws_lo[nb + 4];
#pragma unroll
                for (int mt = 0; mt < 2; ++mt) {
                    mma16816(acc[mt][nt], ah[mt], bh0, bh1);
                    mma16816(acc[mt][nt], al[mt], bh0, bh1);
                    mma16816(acc[mt][nt], ah[mt], bl0, bl1);
                }
            }
        }
        __syncthreads();
    }

    // epilogue: relu, write h and h_n
    const size_t HSIZE = (size_t)BATCH * T * HID;
#pragma unroll
    for (int mt = 0; mt < 2; ++mt) {
        size_t row0 = (size_t)tb * 128 + wm * 32 + mt * 16 + g;
#pragma unroll
        for (int nt = 0; nt < 8; ++nt) {
            int col = ob * 128 + wn * 64 + nt * 8 + tig * 2;
            float2 v0 = make_float2(fmaxf(acc[mt][nt][0], 0.f), fmaxf(acc[mt][nt][1], 0.f));
            float2 v1 = make_float2(fmaxf(acc[mt][nt][2], 0.f), fmaxf(acc[mt][nt][3], 0.f));
            *(float2*)&out[row0 * HID + col] = v0;
            *(float2*)&out[(row0 + 8) * HID + col] = v1;
            if ((row0 & (size_t)(T - 1)) == (size_t)(T - 1))
                *(float2*)&out[HSIZE + (row0 >> 12) * HID + col] = v0;
            if (((row0 + 8) & (size_t)(T - 1)) == (size_t)(T - 1))
                *(float2*)&out[HSIZE + ((row0 + 8) >> 12) * HID + col] = v1;
        }
    }
}

// ---------------------------------------------------------------------------
extern "C" void kernel_launch(void* const* d_in, const int* in_sizes, int n_in,
                              void* d_out, int out_size) {
    const float* x  = (const float*)d_in[0];   // (32, 4096, 256)
    const float* Wu = (const float*)d_in[1];   // (1, 256)
    const float* Wh = (const float*)d_in[2];   // (512, 512)
    const float* H  = (const float*)d_in[3];   // (256, 4096)
    float* out = (float*)d_out;

    (void)in_sizes; (void)n_in; (void)out_size;

    static int smem_set = 0;
    if (!smem_set) {
        cudaFuncSetAttribute(k_conv_hmma, cudaFuncAttributeMaxDynamicSharedMemorySize,
                             CV_SMEM_BYTES);
        cudaFuncSetAttribute(k_gemm2_hmma, cudaFuncAttributeMaxDynamicSharedMemorySize,
                             G2_SMEM_BYTES);
        smem_set = 1;
    }

    k_zero_u<<<(BATCH * USTRIDE + 8 + 255) / 256, 256>>>();
    k_u<<<BATCH * T / 8, 256>>>(x, Wu);
    k_pack_u<<<(BATCH * USTRIDE + 255) / 256, 256>>>();
    k_prep_H<<<(MEM * HPAIR + 255) / 256, 256>>>(H);
    k_prep_W<<<(HID * WPAIR + 255) / 256, 256>>>(Wh);
    k_prep_X<<<(int)(((size_t)BATCH * T * XPAIR + 255) / 256), 256>>>(x);
    k_conv_hmma<<<dim3(NB, 2, BATCH), 256, CV_SMEM_BYTES>>>();
    k_gemm2_hmma<<<dim3(HID / 128, BATCH * T / 128), 256, G2_SMEM_BYTES>>>(out);
}

// round 8
// speedup vs baseline: 3.6757x; 1.6041x over previous
#include <cuda_runtime.h>
#include <cuda_fp16.h>
#include <cstdint>

#define BATCH 32
#define T 4096
#define IN_DIM 256
#define MEM 256
#define HID 512
#define S 128
#define NB 32
#define USTRIDE (T + S)
#define HPAIR (T / 2)               // 2048 pairs per H row
#define MPAIR (MEM / 2)             // 128
#define XPAIR (IN_DIM / 2)          // 128
#define WPAIR ((MEM + IN_DIM) / 2)  // 256

// ---------------- scratch (device globals, 16B aligned for cp.async) --------
__device__ __align__(16) float    g_u[BATCH * USTRIDE + 8];
__device__ __align__(16) unsigned g_up_hi[BATCH * USTRIDE + 8];   // (u[y],u[y-1]) fp16x2
__device__ __align__(16) unsigned g_up_lo[BATCH * USTRIDE + 8];
__device__ __align__(16) unsigned g_Hp[MEM * HPAIR];              // fp16 pairs (hi only)
__device__ __align__(16) unsigned g_Wp[HID * WPAIR];              // fp16 pairs (hi only)
__device__ __align__(16) unsigned g_xp_hi[(size_t)BATCH * T * XPAIR];
__device__ __align__(16) unsigned g_xp_lo[(size_t)BATCH * T * XPAIR];
__device__ __align__(16) unsigned g_mp_hi[(size_t)BATCH * T * MPAIR];
__device__ __align__(16) unsigned g_mp_lo[(size_t)BATCH * T * MPAIR];

// ---------------- helpers ----------------
__device__ __forceinline__ unsigned packh2(float a, float b) {
    __half2 t = __floats2half2_rn(a, b);
    return *reinterpret_cast<unsigned*>(&t);
}
__device__ __forceinline__ float h16rt(float v) {            // round-trip through fp16
    return __half2float(__float2half_rn(v));
}
__device__ __forceinline__ uint32_t smem_u32(const void* p) {
    uint32_t a;
    asm("{ .reg .u64 t; cvta.to.shared.u64 t, %1; cvt.u32.u64 %0, t; }" : "=r"(a) : "l"(p));
    return a;
}
__device__ __forceinline__ void cp16(uint32_t saddr, const void* g) {
    asm volatile("cp.async.cg.shared.global [%0], [%1], 16;" :: "r"(saddr), "l"(g));
}
__device__ __forceinline__ void cp_commit() {
    asm volatile("cp.async.commit_group;" ::: "memory");
}
__device__ __forceinline__ void cp_wait1() {
    asm volatile("cp.async.wait_group 1;" ::: "memory");
}
__device__ __forceinline__ void cp_wait0() {
    asm volatile("cp.async.wait_group 0;" ::: "memory");
}
// D += A(16x16) * B(16x8), fp16 in, fp32 accum
__device__ __forceinline__ void mma16816(float* c, const unsigned* a,
                                         unsigned b0, unsigned b1) {
    asm volatile(
        "mma.sync.aligned.m16n8k16.row.col.f32.f16.f16.f32 "
        "{%0,%1,%2,%3},{%4,%5,%6,%7},{%8,%9},{%0,%1,%2,%3};"
        : "+f"(c[0]), "+f"(c[1]), "+f"(c[2]), "+f"(c[3])
        : "r"(a[0]), "r"(a[1]), "r"(a[2]), "r"(a[3]), "r"(b0), "r"(b1));
}

// ---------------------------------------------------------------------------
__global__ void k_zero_u() {
    int i = blockIdx.x * 256 + threadIdx.x;
    if (i < BATCH * USTRIDE + 8) g_u[i] = 0.0f;
}

__global__ __launch_bounds__(256) void k_u(const float* __restrict__ x,
                                           const float* __restrict__ Wu) {
    __shared__ float w[IN_DIM];
    int tid = threadIdx.x;
    w[tid] = Wu[tid];
    __syncthreads();
    int warp = tid >> 5, lane = tid & 31;
    int row = blockIdx.x * 8 + warp;
    const float* xr = x + (size_t)row * IN_DIM;
    float4 a = *(const float4*)(xr + lane * 4);
    float4 b = *(const float4*)(xr + 128 + lane * 4);
    int j0 = lane * 4;
    float s = a.x * w[j0] + a.y * w[j0 + 1] + a.z * w[j0 + 2] + a.w * w[j0 + 3]
            + b.x * w[128 + j0] + b.y * w[128 + j0 + 1]
            + b.z * w[128 + j0 + 2] + b.w * w[128 + j0 + 3];
#pragma unroll
    for (int off = 16; off; off >>= 1) s += __shfl_xor_sync(0xffffffffu, s, off);
    if (lane == 0) {
        int bb = row >> 12, t = row & (T - 1);
        g_u[bb * USTRIDE + S + t] = fmaxf(s, 0.0f);
    }
}

// reversed pairs: up[y] = (u[y], u[y-1]) as fp16x2 hi + residual lo
__global__ void k_pack_u() {
    int y = blockIdx.x * 256 + threadIdx.x;
    if (y >= BATCH * USTRIDE) return;
    float v0 = g_u[y];
    float v1 = (y > 0) ? g_u[y - 1] : 0.0f;
    float h0 = h16rt(v0), h1 = h16rt(v1);
    g_up_hi[y] = packh2(h0, h1);
    g_up_lo[y] = packh2(v0 - h0, v1 - h1);
}

// Fused prep: x -> fp16 hi/lo pairs; H, W_h -> fp16 pairs (hi only).
__global__ void k_prep_all(const float* __restrict__ x,
                           const float* __restrict__ Wh,
                           const float* __restrict__ H) {
    const size_t XTOT = (size_t)BATCH * T * XPAIR;       // 16,777,216
    const size_t HTOT = (size_t)MEM * HPAIR;             // 524,288
    const size_t WTOT = (size_t)HID * WPAIR;             // 131,072
    size_t i = (size_t)blockIdx.x * 256 + threadIdx.x;
    if (i < XTOT) {
        float v0 = x[2 * i], v1 = x[2 * i + 1];
        float h0 = h16rt(v0), h1 = h16rt(v1);
        g_xp_hi[i] = packh2(h0, h1);
        g_xp_lo[i] = packh2(v0 - h0, v1 - h1);
    } else if (i < XTOT + HTOT) {
        size_t p = i - XTOT;
        g_Hp[p] = packh2(H[2 * p], H[2 * p + 1]);
    } else if (i < XTOT + HTOT + WTOT) {
        size_t p = i - XTOT - HTOT;
        g_Wp[p] = packh2(Wh[2 * p], Wh[2 * p + 1]);
    }
}

// ---------------------------------------------------------------------------
// Conv: per (jb, ks, b) CTA: m tile 128 tau x 128 k, double-buffered cp.async.
// SMEM words: Hbuf[2] of 8704 (hi only), then u[2] of (hi 256 | lo 256).
// ---------------------------------------------------------------------------
#define CV_HW 8704
#define CV_UW0 (2 * CV_HW)                       // 17408
#define CV_SMEM_BYTES ((CV_UW0 + 2 * 512) * 4)   // 73728

__global__ __launch_bounds__(256, 2) void k_conv_hmma() {
    extern __shared__ unsigned sm[];
    uint32_t sb = smem_u32(sm);

    int tid = threadIdx.x, lane = tid & 31, wid = tid >> 5;
    int g = lane >> 2, tig = lane & 3;
    int wm = wid & 3, wn = wid >> 2;
    int jb = NB - 1 - (int)blockIdx.x;
    int ks = blockIdx.y, b = blockIdx.z;

    float acc[2][8][4];
#pragma unroll
    for (int mt = 0; mt < 2; ++mt)
#pragma unroll
        for (int nt = 0; nt < 8; ++nt)
#pragma unroll
            for (int q = 0; q < 4; ++q) acc[mt][nt][q] = 0.0f;

    const int srow = tid >> 1, shalf = tid & 1;
    const size_t hrow = (size_t)(ks * 128 + srow) * HPAIR + shalf * 32;

    auto stage = [&](int i, int p) {
        int l = jb - i;
        const unsigned* shh = &g_Hp[hrow + l * 64];
        uint32_t dh = sb + (uint32_t)(p * CV_HW + srow * 68 + shalf * 32) * 4;
#pragma unroll
        for (int q = 0; q < 8; ++q) cp16(dh + q * 16, shh + q * 4);
        int Wb = b * USTRIDE + i * S;   // window start (pairs); front pad covers t<0
        if (tid < 64)
            cp16(sb + (uint32_t)(CV_UW0 + p * 512 + tid * 4) * 4, &g_up_hi[Wb + tid * 4]);
        else if (tid < 128) {
            int t2 = tid - 64;
            cp16(sb + (uint32_t)(CV_UW0 + p * 512 + 256 + t2 * 4) * 4, &g_up_lo[Wb + t2 * 4]);
        }
        cp_commit();
    };

    stage(0, 0);
    for (int i = 0; i <= jb; ++i) {
        int p = i & 1;
        if (i < jb) { stage(i + 1, p ^ 1); cp_wait1(); }
        else        { cp_wait0(); }
        __syncthreads();

        unsigned* Hs = sm + p * CV_HW;
        unsigned* uw_hi = sm + CV_UW0 + p * 512;
        unsigned* uw_lo = uw_hi + 256;

#pragma unroll
        for (int kk = 0; kk < 8; ++kk) {
            unsigned ah[2][4], al[2][4];
#pragma unroll
            for (int mt = 0; mt < 2; ++mt) {
                int base = 128 + wm * 32 + mt * 16 + g - kk * 16 - 2 * tig;
                ah[mt][0] = uw_hi[base];     al[mt][0] = uw_lo[base];
                ah[mt][1] = uw_hi[base + 8]; al[mt][1] = uw_lo[base + 8];
                ah[mt][2] = uw_hi[base - 8]; al[mt][2] = uw_lo[base - 8];
                ah[mt][3] = ah[mt][0];       al[mt][3] = al[mt][0];   // Toeplitz diag
            }
#pragma unroll
            for (int nt = 0; nt < 8; ++nt) {
                int nb = (wn * 64 + nt * 8 + g) * 68 + kk * 8 + tig;
                unsigned b0 = Hs[nb], b1 = Hs[nb + 4];
#pragma unroll
                for (int mt = 0; mt < 2; ++mt) {
                    mma16816(acc[mt][nt], ah[mt], b0, b1);
                    mma16816(acc[mt][nt], al[mt], b0, b1);
                }
            }
        }
        __syncthreads();
    }

    // epilogue: split m into fp16 hi/lo pairs for gemm2
#pragma unroll
    for (int mt = 0; mt < 2; ++mt) {
        size_t row0 = (size_t)b * T + (size_t)jb * S + wm * 32 + mt * 16 + g;
#pragma unroll
        for (int nt = 0; nt < 8; ++nt) {
            int p = ks * 64 + wn * 32 + nt * 4 + tig;
            float c0 = acc[mt][nt][0], c1 = acc[mt][nt][1];
            float c2 = acc[mt][nt][2], c3 = acc[mt][nt][3];
            float h0 = h16rt(c0), h1 = h16rt(c1), h2 = h16rt(c2), h3 = h16rt(c3);
            g_mp_hi[row0 * MPAIR + p]       = packh2(h0, h1);
            g_mp_lo[row0 * MPAIR + p]       = packh2(c0 - h0, c1 - h1);
            g_mp_hi[(row0 + 8) * MPAIR + p] = packh2(h2, h3);
            g_mp_lo[(row0 + 8) * MPAIR + p] = packh2(c2 - h2, c3 - h3);
        }
    }
}

// ---------------------------------------------------------------------------
// GEMM2: h = relu([m|x] @ W_h^T). CTA = 128 rows x 128 outs, 8 K-chunks of 64,
// double-buffered. Per stage: As_hi | As_lo | Ws (4608 words each).
// ---------------------------------------------------------------------------
#define G2_AS 4608
#define G2_BUF (3 * G2_AS)                // 13824
#define G2_SMEM_BYTES (2 * G2_BUF * 4)    // 110592

__global__ __launch_bounds__(256, 2) void k_gemm2_hmma(float* __restrict__ out) {
    extern __shared__ unsigned sm[];
    uint32_t sb = smem_u32(sm);

    int tid = threadIdx.x, lane = tid & 31, wid = tid >> 5;
    int g = lane >> 2, tig = lane & 3;
    int wm = wid & 3, wn = wid >> 2;
    int ob = blockIdx.x, tb = blockIdx.y;

    float acc[2][8][4];
#pragma unroll
    for (int mt = 0; mt < 2; ++mt)
#pragma unroll
        for (int nt = 0; nt < 8; ++nt)
#pragma unroll
            for (int q = 0; q < 4; ++q) acc[mt][nt][q] = 0.0f;

    const int srow = tid >> 1, shalf = tid & 1;
    const size_t arow = ((size_t)tb * 128 + srow) * 128 + shalf * 16;
    const size_t wrow = (size_t)(ob * 128 + srow) * WPAIR + shalf * 16;

    auto stage = [&](int c, int p) {
        const unsigned *pah, *pal;
        if (c < 4) { pah = &g_mp_hi[arow + c * 32]; pal = &g_mp_lo[arow + c * 32]; }
        else       { pah = &g_xp_hi[arow + (c - 4) * 32]; pal = &g_xp_lo[arow + (c - 4) * 32]; }
        const unsigned* pw = &g_Wp[wrow + c * 32];
        uint32_t d0 = sb + (uint32_t)(p * G2_BUF + srow * 36 + shalf * 16) * 4;
#pragma unroll
        for (int q = 0; q < 4; ++q) {
            cp16(d0 + q * 16,                 pah + q * 4);
            cp16(d0 + G2_AS * 4 + q * 16,     pal + q * 4);
            cp16(d0 + 2 * G2_AS * 4 + q * 16, pw + q * 4);
        }
        cp_commit();
    };

    stage(0, 0);
    for (int c = 0; c < 8; ++c) {
        int p = c & 1;
        if (c < 7) { stage(c + 1, p ^ 1); cp_wait1(); }
        else       { cp_wait0(); }
        __syncthreads();

        unsigned* As_hi = sm + p * G2_BUF;
        unsigned* As_lo = As_hi + G2_AS;
        unsigned* Ws    = As_lo + G2_AS;

#pragma unroll
        for (int kk = 0; kk < 4; ++kk) {
            unsigned ah[2][4], al[2][4];
#pragma unroll
            for (int mt = 0; mt < 2; ++mt) {
                int base = (wm * 32 + mt * 16 + g) * 36 + kk * 8 + tig;
                ah[mt][0] = As_hi[base];              al[mt][0] = As_lo[base];
                ah[mt][1] = As_hi[base + 8 * 36];     al[mt][1] = As_lo[base + 8 * 36];
                ah[mt][2] = As_hi[base + 4];          al[mt][2] = As_lo[base + 4];
                ah[mt][3] = As_hi[base + 8 * 36 + 4]; al[mt][3] = As_lo[base + 8 * 36 + 4];
            }
#pragma unroll
            for (int nt = 0; nt < 8; ++nt) {
                int nb = (wn * 64 + nt * 8 + g) * 36 + kk * 8 + tig;
                unsigned b0 = Ws[nb], b1 = Ws[nb + 4];
#pragma unroll
                for (int mt = 0; mt < 2; ++mt) {
                    mma16816(acc[mt][nt], ah[mt], b0, b1);
                    mma16816(acc[mt][nt], al[mt], b0, b1);
                }
            }
        }
        __syncthreads();
    }

    // epilogue: relu, write h and h_n
    const size_t HSIZE = (size_t)BATCH * T * HID;
#pragma unroll
    for (int mt = 0; mt < 2; ++mt) {
        size_t row0 = (size_t)tb * 128 + wm * 32 + mt * 16 + g;
#pragma unroll
        for (int nt = 0; nt < 8; ++nt) {
            int col = ob * 128 + wn * 64 + nt * 8 + tig * 2;
            float2 v0 = make_float2(fmaxf(acc[mt][nt][0], 0.f), fmaxf(acc[mt][nt][1], 0.f));
            float2 v1 = make_float2(fmaxf(acc[mt][nt][2], 0.f), fmaxf(acc[mt][nt][3], 0.f));
            *(float2*)&out[row0 * HID + col] = v0;
            *(float2*)&out[(row0 + 8) * HID + col] = v1;
            if ((row0 & (size_t)(T - 1)) == (size_t)(T - 1))
                *(float2*)&out[HSIZE + (row0 >> 12) * HID + col] = v0;
            if (((row0 + 8) & (size_t)(T - 1)) == (size_t)(T - 1))
                *(float2*)&out[HSIZE + ((row0 + 8) >> 12) * HID + col] = v1;
        }
    }
}

// ---------------------------------------------------------------------------
extern "C" void kernel_launch(void* const* d_in, const int* in_sizes, int n_in,
                              void* d_out, int out_size) {
    const float* x  = (const float*)d_in[0];   // (32, 4096, 256)
    const float* Wu = (const float*)d_in[1];   // (1, 256)
    const float* Wh = (const float*)d_in[2];   // (512, 512)
    const float* H  = (const float*)d_in[3];   // (256, 4096)
    float* out = (float*)d_out;

    (void)in_sizes; (void)n_in; (void)out_size;

    static int smem_set = 0;
    if (!smem_set) {
        cudaFuncSetAttribute(k_conv_hmma, cudaFuncAttributeMaxDynamicSharedMemorySize,
                             CV_SMEM_BYTES);
        cudaFuncSetAttribute(k_gemm2_hmma, cudaFuncAttributeMaxDynamicSharedMemorySize,
                             G2_SMEM_BYTES);
        smem_set = 1;
    }

    const size_t PREP_TOT = (size_t)BATCH * T * XPAIR + MEM * HPAIR + HID * WPAIR;

    k_zero_u<<<(BATCH * USTRIDE + 8 + 255) / 256, 256>>>();
    k_u<<<BATCH * T / 8, 256>>>(x, Wu);
    k_pack_u<<<(BATCH * USTRIDE + 255) / 256, 256>>>();
    k_prep_all<<<(int)((PREP_TOT + 255) / 256), 256>>>(x, Wh, H);
    k_conv_hmma<<<dim3(NB, 2, BATCH), 256, CV_SMEM_BYTES>>>();
    k_gemm2_hmma<<<dim3(HID / 128, BATCH * T / 128), 256, G2_SMEM_BYTES>>>(out);
}

// round 9
// speedup vs baseline: 3.7610x; 1.0232x over previous
#include <cuda_runtime.h>
#include <cuda_fp16.h>
#include <cstdint>

#define BATCH 32
#define T 4096
#define IN_DIM 256
#define MEM 256
#define HID 512
#define S 128
#define NB 32
#define USTRIDE (T + S)
#define HPAIR (T / 2)               // 2048 pairs per H row
#define MPAIR (MEM / 2)             // 128
#define XPAIR (IN_DIM / 2)          // 128
#define WPAIR ((MEM + IN_DIM) / 2)  // 256

// ---------------- scratch (device globals, 16B aligned for cp.async) --------
__device__ __align__(16) float    g_u[BATCH * USTRIDE + 8];
__device__ __align__(16) unsigned g_up_hi[BATCH * USTRIDE + 8];   // (u[y],u[y-1]) fp16x2
__device__ __align__(16) unsigned g_up_lo[BATCH * USTRIDE + 8];
__device__ __align__(16) unsigned g_Hp[MEM * HPAIR];              // fp16 pairs
__device__ __align__(16) unsigned g_Wp[HID * WPAIR];              // fp16 pairs
__device__ __align__(16) unsigned g_xp_hi[(size_t)BATCH * T * XPAIR];
__device__ __align__(16) unsigned g_xp_lo[(size_t)BATCH * T * XPAIR];
__device__ __align__(16) unsigned g_mp_hi[(size_t)BATCH * T * MPAIR];
__device__ __align__(16) unsigned g_mp_lo[(size_t)BATCH * T * MPAIR];

// ---------------- helpers ----------------
__device__ __forceinline__ unsigned packh2(float a, float b) {
    __half2 t = __floats2half2_rn(a, b);
    return *reinterpret_cast<unsigned*>(&t);
}
__device__ __forceinline__ float h16rt(float v) {
    return __half2float(__float2half_rn(v));
}
__device__ __forceinline__ uint32_t smem_u32(const void* p) {
    uint32_t a;
    asm("{ .reg .u64 t; cvta.to.shared.u64 t, %1; cvt.u32.u64 %0, t; }" : "=r"(a) : "l"(p));
    return a;
}
__device__ __forceinline__ void cp16(uint32_t saddr, const void* g) {
    asm volatile("cp.async.cg.shared.global [%0], [%1], 16;" :: "r"(saddr), "l"(g));
}
__device__ __forceinline__ void cp_commit() {
    asm volatile("cp.async.commit_group;" ::: "memory");
}
__device__ __forceinline__ void cp_wait1() {
    asm volatile("cp.async.wait_group 1;" ::: "memory");
}
// D += A(16x16) * B(16x8), fp16 in, fp32 accum
__device__ __forceinline__ void mma16816(float* c, const unsigned* a,
                                         unsigned b0, unsigned b1) {
    asm volatile(
        "mma.sync.aligned.m16n8k16.row.col.f32.f16.f16.f32 "
        "{%0,%1,%2,%3},{%4,%5,%6,%7},{%8,%9},{%0,%1,%2,%3};"
        : "+f"(c[0]), "+f"(c[1]), "+f"(c[2]), "+f"(c[3])
        : "r"(a[0]), "r"(a[1]), "r"(a[2]), "r"(a[3]), "r"(b0), "r"(b1));
}

// ---------------------------------------------------------------------------
__global__ void k_zero_u() {
    int i = blockIdx.x * 256 + threadIdx.x;
    if (i < BATCH * USTRIDE + 8) g_u[i] = 0.0f;
}

__global__ __launch_bounds__(256) void k_u(const float* __restrict__ x,
                                           const float* __restrict__ Wu) {
    __shared__ float w[IN_DIM];
    int tid = threadIdx.x;
    w[tid] = Wu[tid];
    __syncthreads();
    int warp = tid >> 5, lane = tid & 31;
    int row = blockIdx.x * 8 + warp;
    const float* xr = x + (size_t)row * IN_DIM;
    float4 a = *(const float4*)(xr + lane * 4);
    float4 b = *(const float4*)(xr + 128 + lane * 4);
    int j0 = lane * 4;
    float s = a.x * w[j0] + a.y * w[j0 + 1] + a.z * w[j0 + 2] + a.w * w[j0 + 3]
            + b.x * w[128 + j0] + b.y * w[128 + j0 + 1]
            + b.z * w[128 + j0 + 2] + b.w * w[128 + j0 + 3];
#pragma unroll
    for (int off = 16; off; off >>= 1) s += __shfl_xor_sync(0xffffffffu, s, off);
    if (lane == 0) {
        int bb = row >> 12, t = row & (T - 1);
        g_u[bb * USTRIDE + S + t] = fmaxf(s, 0.0f);
    }
}

__global__ void k_pack_u() {
    int y = blockIdx.x * 256 + threadIdx.x;
    if (y >= BATCH * USTRIDE) return;
    float v0 = g_u[y];
    float v1 = (y > 0) ? g_u[y - 1] : 0.0f;
    float h0 = h16rt(v0), h1 = h16rt(v1);
    g_up_hi[y] = packh2(h0, h1);
    g_up_lo[y] = packh2(v0 - h0, v1 - h1);
}

__global__ void k_prep_all(const float* __restrict__ x,
                           const float* __restrict__ Wh,
                           const float* __restrict__ H) {
    const size_t XTOT = (size_t)BATCH * T * XPAIR;
    const size_t HTOT = (size_t)MEM * HPAIR;
    const size_t WTOT = (size_t)HID * WPAIR;
    size_t i = (size_t)blockIdx.x * 256 + threadIdx.x;
    if (i < XTOT) {
        float v0 = x[2 * i], v1 = x[2 * i + 1];
        float h0 = h16rt(v0), h1 = h16rt(v1);
        g_xp_hi[i] = packh2(h0, h1);
        g_xp_lo[i] = packh2(v0 - h0, v1 - h1);
    } else if (i < XTOT + HTOT) {
        size_t p = i - XTOT;
        g_Hp[p] = packh2(H[2 * p], H[2 * p + 1]);
    } else if (i < XTOT + HTOT + WTOT) {
        size_t p = i - XTOT - HTOT;
        g_Wp[p] = packh2(Wh[2 * p], Wh[2 * p + 1]);
    }
}

// ---------------------------------------------------------------------------
// Conv: per (jb, ks, b) CTA: m tile 128 tau x 128 k.
// 3-stage cp.async pipeline, ONE __syncthreads per iteration.
// Stage layout (words): H 8704 | u_hi 256 | u_lo 256  = 9216
// ---------------------------------------------------------------------------
#define CV_STG 9216
#define CV_SMEM_BYTES (3 * CV_STG * 4)   // 110592

__global__ __launch_bounds__(256, 2) void k_conv_hmma() {
    extern __shared__ unsigned sm[];
    uint32_t sb = smem_u32(sm);

    int tid = threadIdx.x, lane = tid & 31, wid = tid >> 5;
    int g = lane >> 2, tig = lane & 3;
    int wm = wid & 3, wn = wid >> 2;
    int jb = NB - 1 - (int)blockIdx.x;       // heavy tiles first
    int ks = blockIdx.y, b = blockIdx.z;

    float acc[2][8][4];
#pragma unroll
    for (int mt = 0; mt < 2; ++mt)
#pragma unroll
        for (int nt = 0; nt < 8; ++nt)
#pragma unroll
            for (int q = 0; q < 4; ++q) acc[mt][nt][q] = 0.0f;

    const int srow = tid >> 1, shalf = tid & 1;
    const size_t hrow = (size_t)(ks * 128 + srow) * HPAIR + shalf * 32;

    auto stage = [&](int i, int s) {
        if (i <= jb) {
            int l = jb - i;
            const unsigned* shh = &g_Hp[hrow + l * 64];
            uint32_t dh = sb + (uint32_t)(s * CV_STG + srow * 68 + shalf * 32) * 4;
#pragma unroll
            for (int q = 0; q < 8; ++q) cp16(dh + q * 16, shh + q * 4);
            int Wb = b * USTRIDE + i * S;    // window start; front pad covers t<0
            if (tid < 64)
                cp16(sb + (uint32_t)(s * CV_STG + 8704 + tid * 4) * 4,
                     &g_up_hi[Wb + tid * 4]);
            else if (tid < 128) {
                int t2 = tid - 64;
                cp16(sb + (uint32_t)(s * CV_STG + 8960 + t2 * 4) * 4,
                     &g_up_lo[Wb + t2 * 4]);
            }
        }
        cp_commit();   // empty group past end keeps counts uniform
    };

    stage(0, 0);
    stage(1, 1);
    int p = 0;
    for (int i = 0; i <= jb; ++i) {
        cp_wait1();            // buffer i complete (one stage stays in flight)
        __syncthreads();       // all warps finished reading buffer (i-1)%3
        int s2 = p + 2; if (s2 >= 3) s2 -= 3;
        stage(i + 2, s2);      // safe: writes (i-1)%3

        unsigned* Hs    = sm + p * CV_STG;
        unsigned* uw_hi = Hs + 8704;
        unsigned* uw_lo = Hs + 8960;

#pragma unroll
        for (int kk = 0; kk < 8; ++kk) {
            unsigned ah[2][4], al[2][4];
#pragma unroll
            for (int mt = 0; mt < 2; ++mt) {
                int base = 128 + wm * 32 + mt * 16 + g - kk * 16 - 2 * tig;
                ah[mt][0] = uw_hi[base];     al[mt][0] = uw_lo[base];
                ah[mt][1] = uw_hi[base + 8]; al[mt][1] = uw_lo[base + 8];
                ah[mt][2] = uw_hi[base - 8]; al[mt][2] = uw_lo[base - 8];
                ah[mt][3] = ah[mt][0];       al[mt][3] = al[mt][0];   // Toeplitz diag
            }
#pragma unroll
            for (int nt = 0; nt < 8; ++nt) {
                int nb = (wn * 64 + nt * 8 + g) * 68 + kk * 8 + tig;
                unsigned b0 = Hs[nb], b1 = Hs[nb + 4];
#pragma unroll
                for (int mt = 0; mt < 2; ++mt) {
                    mma16816(acc[mt][nt], ah[mt], b0, b1);
                    mma16816(acc[mt][nt], al[mt], b0, b1);
                }
            }
        }
        if (++p == 3) p = 0;
    }

    // epilogue: split m into fp16 hi/lo pairs for gemm2
#pragma unroll
    for (int mt = 0; mt < 2; ++mt) {
        size_t row0 = (size_t)b * T + (size_t)jb * S + wm * 32 + mt * 16 + g;
#pragma unroll
        for (int nt = 0; nt < 8; ++nt) {
            int pp = ks * 64 + wn * 32 + nt * 4 + tig;
            float c0 = acc[mt][nt][0], c1 = acc[mt][nt][1];
            float c2 = acc[mt][nt][2], c3 = acc[mt][nt][3];
            float h0 = h16rt(c0), h1 = h16rt(c1), h2 = h16rt(c2), h3 = h16rt(c3);
            g_mp_hi[row0 * MPAIR + pp]       = packh2(h0, h1);
            g_mp_lo[row0 * MPAIR + pp]       = packh2(c0 - h0, c1 - h1);
            g_mp_hi[(row0 + 8) * MPAIR + pp] = packh2(h2, h3);
            g_mp_lo[(row0 + 8) * MPAIR + pp] = packh2(c2 - h2, c3 - h3);
        }
    }
}

// ---------------------------------------------------------------------------
// GEMM2: h = relu([m|x] @ W_h^T). CTA = 128 rows x 128 outs, 16 K-chunks of 32,
// 3-stage pipeline, one sync per iter. Stage (words): As_hi 2560|As_lo 2560|Ws 2560
// Row stride 20 words (bank map 20g+tig mod 32 distinct for g<8, tig<4).
// ---------------------------------------------------------------------------
#define G2_AS 2560
#define G2_STG (3 * G2_AS)               // 7680 words
#define G2_SMEM_BYTES (3 * G2_STG * 4)   // 92160

__global__ __launch_bounds__(256, 2) void k_gemm2_hmma(float* __restrict__ out) {
    extern __shared__ unsigned sm[];
    uint32_t sb = smem_u32(sm);

    int tid = threadIdx.x, lane = tid & 31, wid = tid >> 5;
    int g = lane >> 2, tig = lane & 3;
    int wm = wid & 3, wn = wid >> 2;
    int ob = blockIdx.x, tb = blockIdx.y;

    float acc[2][8][4];
#pragma unroll
    for (int mt = 0; mt < 2; ++mt)
#pragma unroll
        for (int nt = 0; nt < 8; ++nt)
#pragma unroll
            for (int q = 0; q < 4; ++q) acc[mt][nt][q] = 0.0f;

    const int srow = tid >> 1, shalf = tid & 1;
    const size_t arow0 = ((size_t)tb * 128 + srow) * 128 + shalf * 8;
    const size_t wrow0 = (size_t)(ob * 128 + srow) * WPAIR + shalf * 8;

    auto stage = [&](int c, int s) {
        if (c < 16) {
            const unsigned *pah, *pal;
            if (c < 8) { pah = &g_mp_hi[arow0 + c * 16]; pal = &g_mp_lo[arow0 + c * 16]; }
            else       { pah = &g_xp_hi[arow0 + (c - 8) * 16]; pal = &g_xp_lo[arow0 + (c - 8) * 16]; }
            const unsigned* pw = &g_Wp[wrow0 + c * 16];
            uint32_t d0 = sb + (uint32_t)(s * G2_STG + srow * 20 + shalf * 8) * 4;
#pragma unroll
            for (int q = 0; q < 2; ++q) {
                cp16(d0 + q * 16,                 pah + q * 4);
                cp16(d0 + G2_AS * 4 + q * 16,     pal + q * 4);
                cp16(d0 + 2 * G2_AS * 4 + q * 16, pw + q * 4);
            }
        }
        cp_commit();
    };

    stage(0, 0);
    stage(1, 1);
    int p = 0;
    for (int c = 0; c < 16; ++c) {
        cp_wait1();
        __syncthreads();
        int s2 = p + 2; if (s2 >= 3) s2 -= 3;
        stage(c + 2, s2);

        unsigned* As_hi = sm + p * G2_STG;
        unsigned* As_lo = As_hi + G2_AS;
        unsigned* Ws    = As_lo + G2_AS;

#pragma unroll
        for (int kk = 0; kk < 2; ++kk) {
            unsigned ah[2][4], al[2][4];
#pragma unroll
            for (int mt = 0; mt < 2; ++mt) {
                int base = (wm * 32 + mt * 16 + g) * 20 + kk * 8 + tig;
                ah[mt][0] = As_hi[base];              al[mt][0] = As_lo[base];
                ah[mt][1] = As_hi[base + 8 * 20];     al[mt][1] = As_lo[base + 8 * 20];
                ah[mt][2] = As_hi[base + 4];          al[mt][2] = As_lo[base + 4];
                ah[mt][3] = As_hi[base + 8 * 20 + 4]; al[mt][3] = As_lo[base + 8 * 20 + 4];
            }
#pragma unroll
            for (int nt = 0; nt < 8; ++nt) {
                int nb = (wn * 64 + nt * 8 + g) * 20 + kk * 8 + tig;
                unsigned b0 = Ws[nb], b1 = Ws[nb + 4];
#pragma unroll
                for (int mt = 0; mt < 2; ++mt) {
                    mma16816(acc[mt][nt], ah[mt], b0, b1);
                    mma16816(acc[mt][nt], al[mt], b0, b1);
                }
            }
        }
        if (++p == 3) p = 0;
    }

    // epilogue: relu, write h and h_n
    const size_t HSIZE = (size_t)BATCH * T * HID;
#pragma unroll
    for (int mt = 0; mt < 2; ++mt) {
        size_t row0 = (size_t)tb * 128 + wm * 32 + mt * 16 + g;
#pragma unroll
        for (int nt = 0; nt < 8; ++nt) {
            int col = ob * 128 + wn * 64 + nt * 8 + tig * 2;
            float2 v0 = make_float2(fmaxf(acc[mt][nt][0], 0.f), fmaxf(acc[mt][nt][1], 0.f));
            float2 v1 = make_float2(fmaxf(acc[mt][nt][2], 0.f), fmaxf(acc[mt][nt][3], 0.f));
            *(float2*)&out[row0 * HID + col] = v0;
            *(float2*)&out[(row0 + 8) * HID + col] = v1;
            if ((row0 & (size_t)(T - 1)) == (size_t)(T - 1))
                *(float2*)&out[HSIZE + (row0 >> 12) * HID + col] = v0;
            if (((row0 + 8) & (size_t)(T - 1)) == (size_t)(T - 1))
                *(float2*)&out[HSIZE + ((row0 + 8) >> 12) * HID + col] = v1;
        }
    }
}

// ---------------------------------------------------------------------------
extern "C" void kernel_launch(void* const* d_in, const int* in_sizes, int n_in,
                              void* d_out, int out_size) {
    const float* x  = (const float*)d_in[0];   // (32, 4096, 256)
    const float* Wu = (const float*)d_in[1];   // (1, 256)
    const float* Wh = (const float*)d_in[2];   // (512, 512)
    const float* H  = (const float*)d_in[3];   // (256, 4096)
    float* out = (float*)d_out;

    (void)in_sizes; (void)n_in; (void)out_size;

    static int smem_set = 0;
    if (!smem_set) {
        cudaFuncSetAttribute(k_conv_hmma, cudaFuncAttributeMaxDynamicSharedMemorySize,
                             CV_SMEM_BYTES);
        cudaFuncSetAttribute(k_gemm2_hmma, cudaFuncAttributeMaxDynamicSharedMemorySize,
                             G2_SMEM_BYTES);
        smem_set = 1;
    }

    const size_t PREP_TOT = (size_t)BATCH * T * XPAIR + MEM * HPAIR + HID * WPAIR;

    k_zero_u<<<(BATCH * USTRIDE + 8 + 255) / 256, 256>>>();
    k_u<<<BATCH * T / 8, 256>>>(x, Wu);
    k_pack_u<<<(BATCH * USTRIDE + 255) / 256, 256>>>();
    k_prep_all<<<(int)((PREP_TOT + 255) / 256), 256>>>(x, Wh, H);
    k_conv_hmma<<<dim3(NB, 2, BATCH), 256, CV_SMEM_BYTES>>>();
    k_gemm2_hmma<<<dim3(HID / 128, BATCH * T / 128), 256, G2_SMEM_BYTES>>>(out);
}

// round 10
// speedup vs baseline: 5.5885x; 1.4859x over previous
#include <cuda_runtime.h>
#include <cuda_fp16.h>
#include <cstdint>

#define BATCH 32
#define T 4096
#define IN_DIM 256
#define MEM 256
#define HID 512
#define S 128
#define NB 32
#define USTRIDE (T + S)
#define HPAIR (T / 2)               // 2048 pairs per H row
#define MPAIR (MEM / 2)             // 128
#define XPAIR (IN_DIM / 2)          // 128
#define WPAIR ((MEM + IN_DIM) / 2)  // 256

// ---------------- scratch (device globals, 16B aligned for cp.async) --------
__device__ __align__(16) float    g_u[BATCH * USTRIDE + 8];
__device__ __align__(16) unsigned g_up[BATCH * USTRIDE + 8];      // (u[y],u[y-1]) fp16x2
__device__ __align__(16) unsigned g_Hp[MEM * HPAIR];              // fp16 pairs
__device__ __align__(16) unsigned g_Wp[HID * WPAIR];              // fp16 pairs
__device__ __align__(16) unsigned g_xp[(size_t)BATCH * T * XPAIR];
__device__ __align__(16) unsigned g_mp[(size_t)BATCH * T * MPAIR];

// ---------------- helpers ----------------
__device__ __forceinline__ unsigned packh2(float a, float b) {
    __half2 t = __floats2half2_rn(a, b);
    return *reinterpret_cast<unsigned*>(&t);
}
__device__ __forceinline__ uint32_t smem_u32(const void* p) {
    uint32_t a;
    asm("{ .reg .u64 t; cvta.to.shared.u64 t, %1; cvt.u32.u64 %0, t; }" : "=r"(a) : "l"(p));
    return a;
}
__device__ __forceinline__ void cp16(uint32_t saddr, const void* g) {
    asm volatile("cp.async.cg.shared.global [%0], [%1], 16;" :: "r"(saddr), "l"(g));
}
__device__ __forceinline__ void cp_commit() {
    asm volatile("cp.async.commit_group;" ::: "memory");
}
__device__ __forceinline__ void cp_wait1() {
    asm volatile("cp.async.wait_group 1;" ::: "memory");
}
// D += A(16x16) * B(16x8), fp16 in, fp32 accum
__device__ __forceinline__ void mma16816(float* c, const unsigned* a,
                                         unsigned b0, unsigned b1) {
    asm volatile(
        "mma.sync.aligned.m16n8k16.row.col.f32.f16.f16.f32 "
        "{%0,%1,%2,%3},{%4,%5,%6,%7},{%8,%9},{%0,%1,%2,%3};"
        : "+f"(c[0]), "+f"(c[1]), "+f"(c[2]), "+f"(c[3])
        : "r"(a[0]), "r"(a[1]), "r"(a[2]), "r"(a[3]), "r"(b0), "r"(b1));
}

// ---------------------------------------------------------------------------
__global__ void k_zero_u() {
    int i = blockIdx.x * 256 + threadIdx.x;
    if (i < BATCH * USTRIDE + 8) g_u[i] = 0.0f;
}

__global__ __launch_bounds__(256) void k_u(const float* __restrict__ x,
                                           const float* __restrict__ Wu) {
    __shared__ float w[IN_DIM];
    int tid = threadIdx.x;
    w[tid] = Wu[tid];
    __syncthreads();
    int warp = tid >> 5, lane = tid & 31;
    int row = blockIdx.x * 8 + warp;
    const float* xr = x + (size_t)row * IN_DIM;
    float4 a = *(const float4*)(xr + lane * 4);
    float4 b = *(const float4*)(xr + 128 + lane * 4);
    int j0 = lane * 4;
    float s = a.x * w[j0] + a.y * w[j0 + 1] + a.z * w[j0 + 2] + a.w * w[j0 + 3]
            + b.x * w[128 + j0] + b.y * w[128 + j0 + 1]
            + b.z * w[128 + j0 + 2] + b.w * w[128 + j0 + 3];
#pragma unroll
    for (int off = 16; off; off >>= 1) s += __shfl_xor_sync(0xffffffffu, s, off);
    if (lane == 0) {
        int bb = row >> 12, t = row & (T - 1);
        g_u[bb * USTRIDE + S + t] = fmaxf(s, 0.0f);
    }
}

// reversed pairs: up[y] = (u[y], u[y-1]) as fp16x2
__global__ void k_pack_u() {
    int y = blockIdx.x * 256 + threadIdx.x;
    if (y >= BATCH * USTRIDE) return;
    float v0 = g_u[y];
    float v1 = (y > 0) ? g_u[y - 1] : 0.0f;
    g_up[y] = packh2(v0, v1);
}

// Fused prep: x, H, W_h -> fp16 pairs
__global__ void k_prep_all(const float* __restrict__ x,
                           const float* __restrict__ Wh,
                           const float* __restrict__ H) {
    const size_t XTOT = (size_t)BATCH * T * XPAIR;
    const size_t HTOT = (size_t)MEM * HPAIR;
    const size_t WTOT = (size_t)HID * WPAIR;
    size_t i = (size_t)blockIdx.x * 256 + threadIdx.x;
    if (i < XTOT) {
        g_xp[i] = packh2(x[2 * i], x[2 * i + 1]);
    } else if (i < XTOT + HTOT) {
        size_t p = i - XTOT;
        g_Hp[p] = packh2(H[2 * p], H[2 * p + 1]);
    } else if (i < XTOT + HTOT + WTOT) {
        size_t p = i - XTOT - HTOT;
        g_Wp[p] = packh2(Wh[2 * p], Wh[2 * p + 1]);
    }
}

// ---------------------------------------------------------------------------
// Conv: per (jb, ks, b) CTA: m tile 128 tau x 128 k, pure fp16 single-term.
// 3-stage cp.async pipeline, one __syncthreads per iteration.
// Stage layout (words): H 8704 | u 256  = 8960
// ---------------------------------------------------------------------------
#define CV_STG 8960
#define CV_SMEM_BYTES (3 * CV_STG * 4)   // 107520

__global__ __launch_bounds__(256, 2) void k_conv_hmma() {
    extern __shared__ unsigned sm[];
    uint32_t sb = smem_u32(sm);

    int tid = threadIdx.x, lane = tid & 31, wid = tid >> 5;
    int g = lane >> 2, tig = lane & 3;
    int wm = wid & 3, wn = wid >> 2;
    int jb = NB - 1 - (int)blockIdx.x;       // heavy tiles first
    int ks = blockIdx.y, b = blockIdx.z;

    float acc[2][8][4];
#pragma unroll
    for (int mt = 0; mt < 2; ++mt)
#pragma unroll
        for (int nt = 0; nt < 8; ++nt)
#pragma unroll
            for (int q = 0; q < 4; ++q) acc[mt][nt][q] = 0.0f;

    const int srow = tid >> 1, shalf = tid & 1;
    const size_t hrow = (size_t)(ks * 128 + srow) * HPAIR + shalf * 32;

    auto stage = [&](int i, int s) {
        if (i <= jb) {
            int l = jb - i;
            const unsigned* shh = &g_Hp[hrow + l * 64];
            uint32_t dh = sb + (uint32_t)(s * CV_STG + srow * 68 + shalf * 32) * 4;
#pragma unroll
            for (int q = 0; q < 8; ++q) cp16(dh + q * 16, shh + q * 4);
            int Wb = b * USTRIDE + i * S;    // window start; front pad covers t<0
            if (tid < 64)
                cp16(sb + (uint32_t)(s * CV_STG + 8704 + tid * 4) * 4,
                     &g_up[Wb + tid * 4]);
        }
        cp_commit();   // empty group past end keeps counts uniform
    };

    stage(0, 0);
    stage(1, 1);
    int p = 0;
    for (int i = 0; i <= jb; ++i) {
        cp_wait1();            // buffer i complete (one stage stays in flight)
        __syncthreads();       // all warps finished reading buffer (i-1)%3
        int s2 = p + 2; if (s2 >= 3) s2 -= 3;
        stage(i + 2, s2);      // safe: writes (i-1)%3

        unsigned* Hs = sm + p * CV_STG;
        unsigned* uw = Hs + 8704;

#pragma unroll
        for (int kk = 0; kk < 8; ++kk) {
            unsigned ah[2][4];
#pragma unroll
            for (int mt = 0; mt < 2; ++mt) {
                int base = 128 + wm * 32 + mt * 16 + g - kk * 16 - 2 * tig;
                ah[mt][0] = uw[base];
                ah[mt][1] = uw[base + 8];
                ah[mt][2] = uw[base - 8];
                ah[mt][3] = ah[mt][0];       // Toeplitz diagonal
            }
#pragma unroll
            for (int nt = 0; nt < 8; ++nt) {
                int nb = (wn * 64 + nt * 8 + g) * 68 + kk * 8 + tig;
                unsigned b0 = Hs[nb], b1 = Hs[nb + 4];
                mma16816(acc[0][nt], ah[0], b0, b1);
                mma16816(acc[1][nt], ah[1], b0, b1);
            }
        }
        if (++p == 3) p = 0;
    }

    // epilogue: m -> fp16 pairs for gemm2
#pragma unroll
    for (int mt = 0; mt < 2; ++mt) {
        size_t row0 = (size_t)b * T + (size_t)jb * S + wm * 32 + mt * 16 + g;
#pragma unroll
        for (int nt = 0; nt < 8; ++nt) {
            int pp = ks * 64 + wn * 32 + nt * 4 + tig;
            g_mp[row0 * MPAIR + pp]       = packh2(acc[mt][nt][0], acc[mt][nt][1]);
            g_mp[(row0 + 8) * MPAIR + pp] = packh2(acc[mt][nt][2], acc[mt][nt][3]);
        }
    }
}

// ---------------------------------------------------------------------------
// GEMM2: h = relu([m|x] @ W_h^T). CTA = 128 rows x 128 outs, 8 K-chunks of 64,
// 3-stage pipeline, one sync per iter. Stage (words): As 4608 | Ws 4608
// ---------------------------------------------------------------------------
#define G2_AS 4608
#define G2_STG (2 * G2_AS)               // 9216 words
#define G2_SMEM_BYTES (3 * G2_STG * 4)   // 110592

__global__ __launch_bounds__(256, 2) void k_gemm2_hmma(float* __restrict__ out) {
    extern __shared__ unsigned sm[];
    uint32_t sb = smem_u32(sm);

    int tid = threadIdx.x, lane = tid & 31, wid = tid >> 5;
    int g = lane >> 2, tig = lane & 3;
    int wm = wid & 3, wn = wid >> 2;
    int ob = blockIdx.x, tb = blockIdx.y;

    float acc[2][8][4];
#pragma unroll
    for (int mt = 0; mt < 2; ++mt)
#pragma unroll
        for (int nt = 0; nt < 8; ++nt)
#pragma unroll
            for (int q = 0; q < 4; ++q) acc[mt][nt][q] = 0.0f;

    const int srow = tid >> 1, shalf = tid & 1;
    const size_t arow0 = ((size_t)tb * 128 + srow) * 128 + shalf * 16;
    const size_t wrow0 = (size_t)(ob * 128 + srow) * WPAIR + shalf * 16;

    auto stage = [&](int c, int s) {
        if (c < 8) {
            const unsigned* pa = (c < 4) ? &g_mp[arow0 + c * 32]
                                         : &g_xp[arow0 + (c - 4) * 32];
            const unsigned* pw = &g_Wp[wrow0 + c * 32];
            uint32_t d0 = sb + (uint32_t)(s * G2_STG + srow * 36 + shalf * 16) * 4;
#pragma unroll
            for (int q = 0; q < 4; ++q) {
                cp16(d0 + q * 16,             pa + q * 4);
                cp16(d0 + G2_AS * 4 + q * 16, pw + q * 4);
            }
        }
        cp_commit();
    };

    stage(0, 0);
    stage(1, 1);
    int p = 0;
    for (int c = 0; c < 8; ++c) {
        cp_wait1();
        __syncthreads();
        int s2 = p + 2; if (s2 >= 3) s2 -= 3;
        stage(c + 2, s2);

        unsigned* As = sm + p * G2_STG;
        unsigned* Ws = As + G2_AS;

#pragma unroll
        for (int kk = 0; kk < 4; ++kk) {
            unsigned ah[2][4];
#pragma unroll
            for (int mt = 0; mt < 2; ++mt) {
                int base = (wm * 32 + mt * 16 + g) * 36 + kk * 8 + tig;
                ah[mt][0] = As[base];
                ah[mt][1] = As[base + 8 * 36];
                ah[mt][2] = As[base + 4];
                ah[mt][3] = As[base + 8 * 36 + 4];
            }
#pragma unroll
            for (int nt = 0; nt < 8; ++nt) {
                int nb = (wn * 64 + nt * 8 + g) * 36 + kk * 8 + tig;
                unsigned b0 = Ws[nb], b1 = Ws[nb + 4];
                mma16816(acc[0][nt], ah[0], b0, b1);
                mma16816(acc[1][nt], ah[1], b0, b1);
            }
        }
        if (++p == 3) p = 0;
    }

    // epilogue: relu, write h and h_n
    const size_t HSIZE = (size_t)BATCH * T * HID;
#pragma unroll
    for (int mt = 0; mt < 2; ++mt) {
        size_t row0 = (size_t)tb * 128 + wm * 32 + mt * 16 + g;
#pragma unroll
        for (int nt = 0; nt < 8; ++nt) {
            int col = ob * 128 + wn * 64 + nt * 8 + tig * 2;
            float2 v0 = make_float2(fmaxf(acc[mt][nt][0], 0.f), fmaxf(acc[mt][nt][1], 0.f));
            float2 v1 = make_float2(fmaxf(acc[mt][nt][2], 0.f), fmaxf(acc[mt][nt][3], 0.f));
            *(float2*)&out[row0 * HID + col] = v0;
            *(float2*)&out[(row0 + 8) * HID + col] = v1;
            if ((row0 & (size_t)(T - 1)) == (size_t)(T - 1))
                *(float2*)&out[HSIZE + (row0 >> 12) * HID + col] = v0;
            if (((row0 + 8) & (size_t)(T - 1)) == (size_t)(T - 1))
                *(float2*)&out[HSIZE + ((row0 + 8) >> 12) * HID + col] = v1;
        }
    }
}

// ---------------------------------------------------------------------------
extern "C" void kernel_launch(void* const* d_in, const int* in_sizes, int n_in,
                              void* d_out, int out_size) {
    const float* x  = (const float*)d_in[0];   // (32, 4096, 256)
    const float* Wu = (const float*)d_in[1];   // (1, 256)
    const float* Wh = (const float*)d_in[2];   // (512, 512)
    const float* H  = (const float*)d_in[3];   // (256, 4096)
    float* out = (float*)d_out;

    (void)in_sizes; (void)n_in; (void)out_size;

    static int smem_set = 0;
    if (!smem_set) {
        cudaFuncSetAttribute(k_conv_hmma, cudaFuncAttributeMaxDynamicSharedMemorySize,
                             CV_SMEM_BYTES);
        cudaFuncSetAttribute(k_gemm2_hmma, cudaFuncAttributeMaxDynamicSharedMemorySize,
                             G2_SMEM_BYTES);
        smem_set = 1;
    }

    const size_t PREP_TOT = (size_t)BATCH * T * XPAIR + MEM * HPAIR + HID * WPAIR;

    k_zero_u<<<(BATCH * USTRIDE + 8 + 255) / 256, 256>>>();
    k_u<<<BATCH * T / 8, 256>>>(x, Wu);
    k_pack_u<<<(BATCH * USTRIDE + 255) / 256, 256>>>();
    k_prep_all<<<(int)((PREP_TOT + 255) / 256), 256>>>(x, Wh, H);
    k_conv_hmma<<<dim3(NB, 2, BATCH), 256, CV_SMEM_BYTES>>>();
    k_gemm2_hmma<<<dim3(HID / 128, BATCH * T / 128), 256, G2_SMEM_BYTES>>>(out);
}

// round 11
// speedup vs baseline: 5.8184x; 1.0411x over previous
#include <cuda_runtime.h>
#include <cuda_fp16.h>
#include <cstdint>

#define BATCH 32
#define T 4096
#define IN_DIM 256
#define MEM 256
#define HID 512
#define S 128
#define NB 32
#define USTRIDE (T + S)
#define HPAIR (T / 2)               // 2048 pairs per H row
#define MPAIR (MEM / 2)             // 128
#define XPAIR (IN_DIM / 2)          // 128
#define WPAIR ((MEM + IN_DIM) / 2)  // 256

// ---------------- scratch (device globals, 16B aligned for cp.async) --------
__device__ __align__(16) float    g_u[BATCH * USTRIDE + 8];
__device__ __align__(16) unsigned g_up[BATCH * USTRIDE + 8];      // (u[y],u[y-1]) fp16x2
__device__ __align__(16) unsigned g_Hp[MEM * HPAIR];              // fp16 pairs
__device__ __align__(16) unsigned g_Wp[HID * WPAIR];              // fp16 pairs
__device__ __align__(16) unsigned g_xp[(size_t)BATCH * T * XPAIR];
__device__ __align__(16) unsigned g_mp[(size_t)BATCH * T * MPAIR];

// ---------------- helpers ----------------
__device__ __forceinline__ unsigned packh2(float a, float b) {
    __half2 t = __floats2half2_rn(a, b);
    return *reinterpret_cast<unsigned*>(&t);
}
__device__ __forceinline__ uint32_t smem_u32(const void* p) {
    uint32_t a;
    asm("{ .reg .u64 t; cvta.to.shared.u64 t, %1; cvt.u32.u64 %0, t; }" : "=r"(a) : "l"(p));
    return a;
}
__device__ __forceinline__ void cp16(uint32_t saddr, const void* g) {
    asm volatile("cp.async.cg.shared.global [%0], [%1], 16;" :: "r"(saddr), "l"(g));
}
__device__ __forceinline__ void cp_commit() {
    asm volatile("cp.async.commit_group;" ::: "memory");
}
__device__ __forceinline__ void cp_wait1() {
    asm volatile("cp.async.wait_group 1;" ::: "memory");
}
// D += A(16x16) * B(16x8), fp16 in, fp32 accum
__device__ __forceinline__ void mma16816(float* c, const unsigned* a,
                                         unsigned b0, unsigned b1) {
    asm volatile(
        "mma.sync.aligned.m16n8k16.row.col.f32.f16.f16.f32 "
        "{%0,%1,%2,%3},{%4,%5,%6,%7},{%8,%9},{%0,%1,%2,%3};"
        : "+f"(c[0]), "+f"(c[1]), "+f"(c[2]), "+f"(c[3])
        : "r"(a[0]), "r"(a[1]), "r"(a[2]), "r"(a[3]), "r"(b0), "r"(b1));
}

// ---------------------------------------------------------------------------
__global__ void k_zero_u() {
    int i = blockIdx.x * 256 + threadIdx.x;
    if (i < BATCH * USTRIDE + 8) g_u[i] = 0.0f;
}

// u[b,t] = relu(dot(x[b,t,:], W_u)) — one warp per row.
// FUSED: also emits g_xp (fp16 pairs of x) from the registers already loaded.
__global__ __launch_bounds__(256) void k_u_x(const float* __restrict__ x,
                                             const float* __restrict__ Wu) {
    __shared__ float w[IN_DIM];
    int tid = threadIdx.x;
    w[tid] = Wu[tid];
    __syncthreads();
    int warp = tid >> 5, lane = tid & 31;
    int row = blockIdx.x * 8 + warp;
    const float* xr = x + (size_t)row * IN_DIM;
    float4 a = *(const float4*)(xr + lane * 4);
    float4 b = *(const float4*)(xr + 128 + lane * 4);

    // pack x into fp16 pairs while it's in registers (coalesced uint2 stores)
    {
        uint2 pa = make_uint2(packh2(a.x, a.y), packh2(a.z, a.w));
        uint2 pb = make_uint2(packh2(b.x, b.y), packh2(b.z, b.w));
        *(uint2*)&g_xp[(size_t)row * XPAIR + 2 * lane]      = pa;
        *(uint2*)&g_xp[(size_t)row * XPAIR + 64 + 2 * lane] = pb;
    }

    int j0 = lane * 4;
    float s = a.x * w[j0] + a.y * w[j0 + 1] + a.z * w[j0 + 2] + a.w * w[j0 + 3]
            + b.x * w[128 + j0] + b.y * w[128 + j0 + 1]
            + b.z * w[128 + j0 + 2] + b.w * w[128 + j0 + 3];
#pragma unroll
    for (int off = 16; off; off >>= 1) s += __shfl_xor_sync(0xffffffffu, s, off);
    if (lane == 0) {
        int bb = row >> 12, t = row & (T - 1);
        g_u[bb * USTRIDE + S + t] = fmaxf(s, 0.0f);
    }
}

// reversed pairs: up[y] = (u[y], u[y-1]) as fp16x2
__global__ void k_pack_u() {
    int y = blockIdx.x * 256 + threadIdx.x;
    if (y >= BATCH * USTRIDE) return;
    float v0 = g_u[y];
    float v1 = (y > 0) ? g_u[y - 1] : 0.0f;
    g_up[y] = packh2(v0, v1);
}

// Prep H, W_h -> fp16 pairs (x handled in k_u_x)
__global__ void k_prep_HW(const float* __restrict__ Wh,
                          const float* __restrict__ H) {
    const size_t HTOT = (size_t)MEM * HPAIR;             // 524288
    const size_t WTOT = (size_t)HID * WPAIR;             // 131072
    size_t i = (size_t)blockIdx.x * 256 + threadIdx.x;
    if (i < HTOT) {
        g_Hp[i] = packh2(H[2 * i], H[2 * i + 1]);
    } else if (i < HTOT + WTOT) {
        size_t p = i - HTOT;
        g_Wp[p] = packh2(Wh[2 * p], Wh[2 * p + 1]);
    }
}

// ---------------------------------------------------------------------------
// Conv: per (jb, ks, b) CTA: m tile 128 tau x 128 k, pure fp16 single-term.
// 3-stage cp.async pipeline, one __syncthreads per iteration.
// Stage layout (words): H 8704 | u 256  = 8960
// ---------------------------------------------------------------------------
#define CV_STG 8960
#define CV_SMEM_BYTES (3 * CV_STG * 4)   // 107520

__global__ __launch_bounds__(256, 2) void k_conv_hmma() {
    extern __shared__ unsigned sm[];
    uint32_t sb = smem_u32(sm);

    int tid = threadIdx.x, lane = tid & 31, wid = tid >> 5;
    int g = lane >> 2, tig = lane & 3;
    int wm = wid & 3, wn = wid >> 2;
    int jb = NB - 1 - (int)blockIdx.x;       // heavy tiles first
    int ks = blockIdx.y, b = blockIdx.z;

    float acc[2][8][4];
#pragma unroll
    for (int mt = 0; mt < 2; ++mt)
#pragma unroll
        for (int nt = 0; nt < 8; ++nt)
#pragma unroll
            for (int q = 0; q < 4; ++q) acc[mt][nt][q] = 0.0f;

    const int srow = tid >> 1, shalf = tid & 1;
    const size_t hrow = (size_t)(ks * 128 + srow) * HPAIR + shalf * 32;

    auto stage = [&](int i, int s) {
        if (i <= jb) {
            int l = jb - i;
            const unsigned* shh = &g_Hp[hrow + l * 64];
            uint32_t dh = sb + (uint32_t)(s * CV_STG + srow * 68 + shalf * 32) * 4;
#pragma unroll
            for (int q = 0; q < 8; ++q) cp16(dh + q * 16, shh + q * 4);
            int Wb = b * USTRIDE + i * S;    // window start; front pad covers t<0
            if (tid < 64)
                cp16(sb + (uint32_t)(s * CV_STG + 8704 + tid * 4) * 4,
                     &g_up[Wb + tid * 4]);
        }
        cp_commit();   // empty group past end keeps counts uniform
    };

    stage(0, 0);
    stage(1, 1);
    int p = 0;
    for (int i = 0; i <= jb; ++i) {
        cp_wait1();            // buffer i complete (one stage stays in flight)
        __syncthreads();       // all warps finished reading buffer (i-1)%3
        int s2 = p + 2; if (s2 >= 3) s2 -= 3;
        stage(i + 2, s2);      // safe: writes (i-1)%3

        unsigned* Hs = sm + p * CV_STG;
        unsigned* uw = Hs + 8704;

#pragma unroll
        for (int kk = 0; kk < 8; ++kk) {
            unsigned ah[2][4];
#pragma unroll
            for (int mt = 0; mt < 2; ++mt) {
                int base = 128 + wm * 32 + mt * 16 + g - kk * 16 - 2 * tig;
                ah[mt][0] = uw[base];
                ah[mt][1] = uw[base + 8];
                ah[mt][2] = uw[base - 8];
                ah[mt][3] = ah[mt][0];       // Toeplitz diagonal
            }
#pragma unroll
            for (int nt = 0; nt < 8; ++nt) {
                int nb = (wn * 64 + nt * 8 + g) * 68 + kk * 8 + tig;
                unsigned b0 = Hs[nb], b1 = Hs[nb + 4];
                mma16816(acc[0][nt], ah[0], b0, b1);
                mma16816(acc[1][nt], ah[1], b0, b1);
            }
        }
        if (++p == 3) p = 0;
    }

    // epilogue: m -> fp16 pairs for gemm2
#pragma unroll
    for (int mt = 0; mt < 2; ++mt) {
        size_t row0 = (size_t)b * T + (size_t)jb * S + wm * 32 + mt * 16 + g;
#pragma unroll
        for (int nt = 0; nt < 8; ++nt) {
            int pp = ks * 64 + wn * 32 + nt * 4 + tig;
            g_mp[row0 * MPAIR + pp]       = packh2(acc[mt][nt][0], acc[mt][nt][1]);
            g_mp[(row0 + 8) * MPAIR + pp] = packh2(acc[mt][nt][2], acc[mt][nt][3]);
        }
    }
}

// ---------------------------------------------------------------------------
// GEMM2: h = relu([m|x] @ W_h^T). CTA = 128 rows x 128 outs, 8 K-chunks of 64,
// 3-stage pipeline, one sync per iter. Stage (words): As 4608 | Ws 4608
// ---------------------------------------------------------------------------
#define G2_AS 4608
#define G2_STG (2 * G2_AS)               // 9216 words
#define G2_SMEM_BYTES (3 * G2_STG * 4)   // 110592

__global__ __launch_bounds__(256, 2) void k_gemm2_hmma(float* __restrict__ out) {
    extern __shared__ unsigned sm[];
    uint32_t sb = smem_u32(sm);

    int tid = threadIdx.x, lane = tid & 31, wid = tid >> 5;
    int g = lane >> 2, tig = lane & 3;
    int wm = wid & 3, wn = wid >> 2;
    int ob = blockIdx.x, tb = blockIdx.y;

    float acc[2][8][4];
#pragma unroll
    for (int mt = 0; mt < 2; ++mt)
#pragma unroll
        for (int nt = 0; nt < 8; ++nt)
#pragma unroll
            for (int q = 0; q < 4; ++q) acc[mt][nt][q] = 0.0f;

    const int srow = tid >> 1, shalf = tid & 1;
    const size_t arow0 = ((size_t)tb * 128 + srow) * 128 + shalf * 16;
    const size_t wrow0 = (size_t)(ob * 128 + srow) * WPAIR + shalf * 16;

    auto stage = [&](int c, int s) {
        if (c < 8) {
            const unsigned* pa = (c < 4) ? &g_mp[arow0 + c * 32]
                                         : &g_xp[arow0 + (c - 4) * 32];
            const unsigned* pw = &g_Wp[wrow0 + c * 32];
            uint32_t d0 = sb + (uint32_t)(s * G2_STG + srow * 36 + shalf * 16) * 4;
#pragma unroll
            for (int q = 0; q < 4; ++q) {
                cp16(d0 + q * 16,             pa + q * 4);
                cp16(d0 + G2_AS * 4 + q * 16, pw + q * 4);
            }
        }
        cp_commit();
    };

    stage(0, 0);
    stage(1, 1);
    int p = 0;
    for (int c = 0; c < 8; ++c) {
        cp_wait1();
        __syncthreads();
        int s2 = p + 2; if (s2 >= 3) s2 -= 3;
        stage(c + 2, s2);

        unsigned* As = sm + p * G2_STG;
        unsigned* Ws = As + G2_AS;

#pragma unroll
        for (int kk = 0; kk < 4; ++kk) {
            unsigned ah[2][4];
#pragma unroll
            for (int mt = 0; mt < 2; ++mt) {
                int base = (wm * 32 + mt * 16 + g) * 36 + kk * 8 + tig;
                ah[mt][0] = As[base];
                ah[mt][1] = As[base + 8 * 36];
                ah[mt][2] = As[base + 4];
                ah[mt][3] = As[base + 8 * 36 + 4];
            }
#pragma unroll
            for (int nt = 0; nt < 8; ++nt) {
                int nb = (wn * 64 + nt * 8 + g) * 36 + kk * 8 + tig;
                unsigned b0 = Ws[nb], b1 = Ws[nb + 4];
                mma16816(acc[0][nt], ah[0], b0, b1);
                mma16816(acc[1][nt], ah[1], b0, b1);
            }
        }
        if (++p == 3) p = 0;
    }

    // epilogue: relu, write h and h_n
    const size_t HSIZE = (size_t)BATCH * T * HID;
#pragma unroll
    for (int mt = 0; mt < 2; ++mt) {
        size_t row0 = (size_t)tb * 128 + wm * 32 + mt * 16 + g;
#pragma unroll
        for (int nt = 0; nt < 8; ++nt) {
            int col = ob * 128 + wn * 64 + nt * 8 + tig * 2;
            float2 v0 = make_float2(fmaxf(acc[mt][nt][0], 0.f), fmaxf(acc[mt][nt][1], 0.f));
            float2 v1 = make_float2(fmaxf(acc[mt][nt][2], 0.f), fmaxf(acc[mt][nt][3], 0.f));
            *(float2*)&out[row0 * HID + col] = v0;
            *(float2*)&out[(row0 + 8) * HID + col] = v1;
            if ((row0 & (size_t)(T - 1)) == (size_t)(T - 1))
                *(float2*)&out[HSIZE + (row0 >> 12) * HID + col] = v0;
            if (((row0 + 8) & (size_t)(T - 1)) == (size_t)(T - 1))
                *(float2*)&out[HSIZE + ((row0 + 8) >> 12) * HID + col] = v1;
        }
    }
}

// ---------------------------------------------------------------------------
extern "C" void kernel_launch(void* const* d_in, const int* in_sizes, int n_in,
                              void* d_out, int out_size) {
    const float* x  = (const float*)d_in[0];   // (32, 4096, 256)
    const float* Wu = (const float*)d_in[1];   // (1, 256)
    const float* Wh = (const float*)d_in[2];   // (512, 512)
    const float* H  = (const float*)d_in[3];   // (256, 4096)
    float* out = (float*)d_out;

    (void)in_sizes; (void)n_in; (void)out_size;

    static int smem_set = 0;
    if (!smem_set) {
        cudaFuncSetAttribute(k_conv_hmma, cudaFuncAttributeMaxDynamicSharedMemorySize,
                             CV_SMEM_BYTES);
        cudaFuncSetAttribute(k_gemm2_hmma, cudaFuncAttributeMaxDynamicSharedMemorySize,
                             G2_SMEM_BYTES);
        smem_set = 1;
    }

    const size_t PREP_HW = (size_t)MEM * HPAIR + HID * WPAIR;

    k_zero_u<<<(BATCH * USTRIDE + 8 + 255) / 256, 256>>>();
    k_prep_HW<<<(int)((PREP_HW + 255) / 256), 256>>>(Wh, H);
    k_u_x<<<BATCH * T / 8, 256>>>(x, Wu);
    k_pack_u<<<(BATCH * USTRIDE + 255) / 256, 256>>>();
    k_conv_hmma<<<dim3(NB, 2, BATCH), 256, CV_SMEM_BYTES>>>();
    k_gemm2_hmma<<<dim3(HID / 128, BATCH * T / 128), 256, G2_SMEM_BYTES>>>(out);
}

// round 12
// speedup vs baseline: 6.0927x; 1.0472x over previous
#include <cuda_runtime.h>
#include <cuda_fp16.h>
#include <cstdint>

#define BATCH 32
#define T 4096
#define IN_DIM 256
#define MEM 256
#define HID 512
#define S 128
#define NB 32
#define USTRIDE (T + S)
#define HPAIR (T / 2)               // 2048 pairs per H row
#define MPAIR (MEM / 2)             // 128
#define XPAIR (IN_DIM / 2)          // 128
#define WPAIR ((MEM + IN_DIM) / 2)  // 256

#define UX_BLOCKS (BATCH * T / 8)                   // 16384 CTAs for u/x part
#define HTOT ((size_t)MEM * HPAIR)                  // 524288
#define WTOT ((size_t)HID * WPAIR)                  // 131072
#define PREP_BLOCKS ((int)((HTOT + WTOT + 255) / 256))  // 2560

// ---------------- scratch (device globals, 16B aligned for cp.async) --------
__device__ __align__(16) float    g_u[BATCH * USTRIDE + 8];
__device__ __align__(16) unsigned g_up[BATCH * USTRIDE + 8];      // (u[y],u[y-1]) fp16x2
__device__ __align__(16) unsigned g_Hp[MEM * HPAIR];              // fp16 pairs
__device__ __align__(16) unsigned g_Wp[HID * WPAIR];              // fp16 pairs
__device__ __align__(16) unsigned g_xp[(size_t)BATCH * T * XPAIR];
__device__ __align__(16) unsigned g_mp[(size_t)BATCH * T * MPAIR];

// ---------------- helpers ----------------
__device__ __forceinline__ unsigned packh2(float a, float b) {
    __half2 t = __floats2half2_rn(a, b);
    return *reinterpret_cast<unsigned*>(&t);
}
__device__ __forceinline__ uint32_t smem_u32(const void* p) {
    uint32_t a;
    asm("{ .reg .u64 t; cvta.to.shared.u64 t, %1; cvt.u32.u64 %0, t; }" : "=r"(a) : "l"(p));
    return a;
}
__device__ __forceinline__ void cp16(uint32_t saddr, const void* g) {
    asm volatile("cp.async.cg.shared.global [%0], [%1], 16;" :: "r"(saddr), "l"(g));
}
__device__ __forceinline__ void cp_commit() {
    asm volatile("cp.async.commit_group;" ::: "memory");
}
__device__ __forceinline__ void cp_wait1() {
    asm volatile("cp.async.wait_group 1;" ::: "memory");
}
// D += A(16x16) * B(16x8), fp16 in, fp32 accum
__device__ __forceinline__ void mma16816(float* c, const unsigned* a,
                                         unsigned b0, unsigned b1) {
    asm volatile(
        "mma.sync.aligned.m16n8k16.row.col.f32.f16.f16.f32 "
        "{%0,%1,%2,%3},{%4,%5,%6,%7},{%8,%9},{%0,%1,%2,%3};"
        : "+f"(c[0]), "+f"(c[1]), "+f"(c[2]), "+f"(c[3])
        : "r"(a[0]), "r"(a[1]), "r"(a[2]), "r"(a[3]), "r"(b0), "r"(b1));
}

// ---------------------------------------------------------------------------
// Front kernel: CTAs [0, UX_BLOCKS) compute u=relu(x@Wu) and pack x -> fp16;
// CTAs [UX_BLOCKS, ...) pack H and W_h -> fp16 pairs. Independent ranges.
// ---------------------------------------------------------------------------
__global__ __launch_bounds__(256) void k_front(const float* __restrict__ x,
                                               const float* __restrict__ Wu,
                                               const float* __restrict__ Wh,
                                               const float* __restrict__ H) {
    int bx = blockIdx.x;
    if (bx < UX_BLOCKS) {
        __shared__ float w[IN_DIM];
        int tid = threadIdx.x;
        w[tid] = Wu[tid];
        __syncthreads();
        int warp = tid >> 5, lane = tid & 31;
        int row = bx * 8 + warp;
        const float* xr = x + (size_t)row * IN_DIM;
        float4 a = *(const float4*)(xr + lane * 4);
        float4 b = *(const float4*)(xr + 128 + lane * 4);

        // pack x into fp16 pairs while in registers (coalesced uint2 stores)
        {
            uint2 pa = make_uint2(packh2(a.x, a.y), packh2(a.z, a.w));
            uint2 pb = make_uint2(packh2(b.x, b.y), packh2(b.z, b.w));
            *(uint2*)&g_xp[(size_t)row * XPAIR + 2 * lane]      = pa;
            *(uint2*)&g_xp[(size_t)row * XPAIR + 64 + 2 * lane] = pb;
        }

        int j0 = lane * 4;
        float s = a.x * w[j0] + a.y * w[j0 + 1] + a.z * w[j0 + 2] + a.w * w[j0 + 3]
                + b.x * w[128 + j0] + b.y * w[128 + j0 + 1]
                + b.z * w[128 + j0 + 2] + b.w * w[128 + j0 + 3];
#pragma unroll
        for (int off = 16; off; off >>= 1) s += __shfl_xor_sync(0xffffffffu, s, off);
        if (lane == 0) {
            int bb = row >> 12, t = row & (T - 1);
            g_u[bb * USTRIDE + S + t] = fmaxf(s, 0.0f);
        }
    } else {
        size_t i = (size_t)(bx - UX_BLOCKS) * 256 + threadIdx.x;
        if (i < HTOT) {
            g_Hp[i] = packh2(H[2 * i], H[2 * i + 1]);
        } else if (i < HTOT + WTOT) {
            size_t p = i - HTOT;
            g_Wp[p] = packh2(Wh[2 * p], Wh[2 * p + 1]);
        }
    }
}

// reversed pairs: up[y] = (u[y], u[y-1]) as fp16x2, pads produce exact zeros
// (never reads uninitialized g_u; no zero-fill kernel needed)
__global__ void k_pack_u() {
    int y = blockIdx.x * 256 + threadIdx.x;
    if (y >= BATCH * USTRIDE) return;
    int local = y % USTRIDE;
    float v0 = 0.0f, v1 = 0.0f;
    if (local >= S) v0 = g_u[y];
    if (local > S)  v1 = g_u[y - 1];
    g_up[y] = packh2(v0, v1);
}

// ---------------------------------------------------------------------------
// Conv: m tile 128 tau x 128 k, pure fp16 single-term HMMA.
// Global LPT order: bid 0..63 -> jb=31, 64..127 -> jb=30, ...
// i==0 iteration is block-lower-triangular: skip all-zero (kk, mt) blocks.
// 3-stage cp.async pipeline, one __syncthreads per iteration.
// Stage layout (words): H 8704 | u 256  = 8960
// ---------------------------------------------------------------------------
#define CV_STG 8960
#define CV_SMEM_BYTES (3 * CV_STG * 4)   // 107520

__global__ __launch_bounds__(256, 2) void k_conv_hmma() {
    extern __shared__ unsigned sm[];
    uint32_t sb = smem_u32(sm);

    int tid = threadIdx.x, lane = tid & 31, wid = tid >> 5;
    int g = lane >> 2, tig = lane & 3;
    int wm = wid & 3, wn = wid >> 2;

    // LPT: heaviest tiles (jb=31) occupy the first 64 bids, etc.
    int bid = blockIdx.x + 32 * (blockIdx.y + 2 * blockIdx.z);
    int jb = NB - 1 - (bid >> 6);
    int idx = bid & 63;
    int ks = idx & 1, b = idx >> 1;

    float acc[2][8][4];
#pragma unroll
    for (int mt = 0; mt < 2; ++mt)
#pragma unroll
        for (int nt = 0; nt < 8; ++nt)
#pragma unroll
            for (int q = 0; q < 4; ++q) acc[mt][nt][q] = 0.0f;

    const int srow = tid >> 1, shalf = tid & 1;
    const size_t hrow = (size_t)(ks * 128 + srow) * HPAIR + shalf * 32;

    auto stage = [&](int i, int s) {
        if (i <= jb) {
            int l = jb - i;
            const unsigned* shh = &g_Hp[hrow + l * 64];
            uint32_t dh = sb + (uint32_t)(s * CV_STG + srow * 68 + shalf * 32) * 4;
#pragma unroll
            for (int q = 0; q < 8; ++q) cp16(dh + q * 16, shh + q * 4);
            int Wb = b * USTRIDE + i * S;    // window start; front pad covers t<0
            if (tid < 64)
                cp16(sb + (uint32_t)(s * CV_STG + 8704 + tid * 4) * 4,
                     &g_up[Wb + tid * 4]);
        }
        cp_commit();   // empty group past end keeps counts uniform
    };

    stage(0, 0);
    stage(1, 1);
    int p = 0;
    for (int i = 0; i <= jb; ++i) {
        cp_wait1();            // buffer i complete (one stage stays in flight)
        __syncthreads();       // all warps finished reading buffer (i-1)%3
        int s2 = p + 2; if (s2 >= 3) s2 -= 3;
        stage(i + 2, s2);      // safe: writes (i-1)%3

        unsigned* Hs = sm + p * CV_STG;
        unsigned* uw = Hs + 8704;

#pragma unroll
        for (int kk = 0; kk < 8; ++kk) {
            // i==0: u block 0 is lower-triangular in (tau, d); blocks with
            // kk*16 > tau_max are exactly zero -> skip (warp-uniform).
            bool sk0 = (i == 0) && (kk > 2 * wm);
            bool sk1 = (i == 0) && (kk > 2 * wm + 1);
            unsigned ah[2][4];
#pragma unroll
            for (int mt = 0; mt < 2; ++mt) {
                bool sk = mt ? sk1 : sk0;
                if (!sk) {
                    int base = 128 + wm * 32 + mt * 16 + g - kk * 16 - 2 * tig;
                    ah[mt][0] = uw[base];
                    ah[mt][1] = uw[base + 8];
                    ah[mt][2] = uw[base - 8];
                    ah[mt][3] = ah[mt][0];   // Toeplitz diagonal
                }
            }
#pragma unroll
            for (int nt = 0; nt < 8; ++nt) {
                int nb = (wn * 64 + nt * 8 + g) * 68 + kk * 8 + tig;
                unsigned b0 = Hs[nb], b1 = Hs[nb + 4];
                if (!sk0) mma16816(acc[0][nt], ah[0], b0, b1);
                if (!sk1) mma16816(acc[1][nt], ah[1], b0, b1);
            }
        }
        if (++p == 3) p = 0;
    }

    // epilogue: m -> fp16 pairs for gemm2
#pragma unroll
    for (int mt = 0; mt < 2; ++mt) {
        size_t row0 = (size_t)b * T + (size_t)jb * S + wm * 32 + mt * 16 + g;
#pragma unroll
        for (int nt = 0; nt < 8; ++nt) {
            int pp = ks * 64 + wn * 32 + nt * 4 + tig;
            g_mp[row0 * MPAIR + pp]       = packh2(acc[mt][nt][0], acc[mt][nt][1]);
            g_mp[(row0 + 8) * MPAIR + pp] = packh2(acc[mt][nt][2], acc[mt][nt][3]);
        }
    }
}

// ---------------------------------------------------------------------------
// GEMM2: h = relu([m|x] @ W_h^T). CTA = 128 rows x 128 outs, 8 K-chunks of 64,
// 3-stage pipeline, one sync per iter. Stage (words): As 4608 | Ws 4608
// ---------------------------------------------------------------------------
#define G2_AS 4608
#define G2_STG (2 * G2_AS)               // 9216 words
#define G2_SMEM_BYTES (3 * G2_STG * 4)   // 110592

__global__ __launch_bounds__(256, 2) void k_gemm2_hmma(float* __restrict__ out) {
    extern __shared__ unsigned sm[];
    uint32_t sb = smem_u32(sm);

    int tid = threadIdx.x, lane = tid & 31, wid = tid >> 5;
    int g = lane >> 2, tig = lane & 3;
    int wm = wid & 3, wn = wid >> 2;
    int ob = blockIdx.x, tb = blockIdx.y;

    float acc[2][8][4];
#pragma unroll
    for (int mt = 0; mt < 2; ++mt)
#pragma unroll
        for (int nt = 0; nt < 8; ++nt)
#pragma unroll
            for (int q = 0; q < 4; ++q) acc[mt][nt][q] = 0.0f;

    const int srow = tid >> 1, shalf = tid & 1;
    const size_t arow0 = ((size_t)tb * 128 + srow) * 128 + shalf * 16;
    const size_t wrow0 = (size_t)(ob * 128 + srow) * WPAIR + shalf * 16;

    auto stage = [&](int c, int s) {
        if (c < 8) {
            const unsigned* pa = (c < 4) ? &g_mp[arow0 + c * 32]
                                         : &g_xp[arow0 + (c - 4) * 32];
            const unsigned* pw = &g_Wp[wrow0 + c * 32];
            uint32_t d0 = sb + (uint32_t)(s * G2_STG + srow * 36 + shalf * 16) * 4;
#pragma unroll
            for (int q = 0; q < 4; ++q) {
                cp16(d0 + q * 16,             pa + q * 4);
                cp16(d0 + G2_AS * 4 + q * 16, pw + q * 4);
            }
        }
        cp_commit();
    };

    stage(0, 0);
    stage(1, 1);
    int p = 0;
    for (int c = 0; c < 8; ++c) {
        cp_wait1();
        __syncthreads();
        int s2 = p + 2; if (s2 >= 3) s2 -= 3;
        stage(c + 2, s2);

        unsigned* As = sm + p * G2_STG;
        unsigned* Ws = As + G2_AS;

#pragma unroll
        for (int kk = 0; kk < 4; ++kk) {
            unsigned ah[2][4];
#pragma unroll
            for (int mt = 0; mt < 2; ++mt) {
                int base = (wm * 32 + mt * 16 + g) * 36 + kk * 8 + tig;
                ah[mt][0] = As[base];
                ah[mt][1] = As[base + 8 * 36];
                ah[mt][2] = As[base + 4];
                ah[mt][3] = As[base + 8 * 36 + 4];
            }
#pragma unroll
            for (int nt = 0; nt < 8; ++nt) {
                int nb = (wn * 64 + nt * 8 + g) * 36 + kk * 8 + tig;
                unsigned b0 = Ws[nb], b1 = Ws[nb + 4];
                mma16816(acc[0][nt], ah[0], b0, b1);
                mma16816(acc[1][nt], ah[1], b0, b1);
            }
        }
        if (++p == 3) p = 0;
    }

    // epilogue: relu, write h and h_n
    const size_t HSIZE = (size_t)BATCH * T * HID;
#pragma unroll
    for (int mt = 0; mt < 2; ++mt) {
        size_t row0 = (size_t)tb * 128 + wm * 32 + mt * 16 + g;
#pragma unroll
        for (int nt = 0; nt < 8; ++nt) {
            int col = ob * 128 + wn * 64 + nt * 8 + tig * 2;
            float2 v0 = make_float2(fmaxf(acc[mt][nt][0], 0.f), fmaxf(acc[mt][nt][1], 0.f));
            float2 v1 = make_float2(fmaxf(acc[mt][nt][2], 0.f), fmaxf(acc[mt][nt][3], 0.f));
            *(float2*)&out[row0 * HID + col] = v0;
            *(float2*)&out[(row0 + 8) * HID + col] = v1;
            if ((row0 & (size_t)(T - 1)) == (size_t)(T - 1))
                *(float2*)&out[HSIZE + (row0 >> 12) * HID + col] = v0;
            if (((row0 + 8) & (size_t)(T - 1)) == (size_t)(T - 1))
                *(float2*)&out[HSIZE + ((row0 + 8) >> 12) * HID + col] = v1;
        }
    }
}

// ---------------------------------------------------------------------------
extern "C" void kernel_launch(void* const* d_in, const int* in_sizes, int n_in,
                              void* d_out, int out_size) {
    const float* x  = (const float*)d_in[0];   // (32, 4096, 256)
    const float* Wu = (const float*)d_in[1];   // (1, 256)
    const float* Wh = (const float*)d_in[2];   // (512, 512)
    const float* H  = (const float*)d_in[3];   // (256, 4096)
    float* out = (float*)d_out;

    (void)in_sizes; (void)n_in; (void)out_size;

    static int smem_set = 0;
    if (!smem_set) {
        cudaFuncSetAttribute(k_conv_hmma, cudaFuncAttributeMaxDynamicSharedMemorySize,
                             CV_SMEM_BYTES);
        cudaFuncSetAttribute(k_gemm2_hmma, cudaFuncAttributeMaxDynamicSharedMemorySize,
                             G2_SMEM_BYTES);
        smem_set = 1;
    }

    k_front<<<UX_BLOCKS + PREP_BLOCKS, 256>>>(x, Wu, Wh, H);
    k_pack_u<<<(BATCH * USTRIDE + 255) / 256, 256>>>();
    k_conv_hmma<<<dim3(NB, 2, BATCH), 256, CV_SMEM_BYTES>>>();
    k_gemm2_hmma<<<dim3(HID / 128, BATCH * T / 128), 256, G2_SMEM_BYTES>>>(out);
}

// round 13
// speedup vs baseline: 6.3114x; 1.0359x over previous
#include <cuda_runtime.h>
#include <cuda_fp16.h>
#include <cstdint>

#define BATCH 32
#define T 4096
#define IN_DIM 256
#define MEM 256
#define HID 512
#define S 128
#define NB 32
#define USTRIDE (T + S)
#define HPAIR (T / 2)               // 2048 pairs per H row
#define MPAIR (MEM / 2)             // 128
#define XPAIR (IN_DIM / 2)          // 128
#define WPAIR ((MEM + IN_DIM) / 2)  // 256

#define UX_BLOCKS (BATCH * T / 8)                   // 16384 CTAs for u/x part
#define HTOT ((size_t)MEM * HPAIR)                  // 524288
#define WTOT ((size_t)HID * WPAIR)                  // 131072
#define PREP_BLOCKS ((int)((HTOT + WTOT + 255) / 256))  // 2560

// ---------------- scratch (device globals, 16B aligned for cp.async) --------
__device__ __align__(16) float    g_u[BATCH * USTRIDE + 8];
__device__ __align__(16) unsigned g_up[BATCH * USTRIDE + 8];      // (u[y],u[y-1]) fp16x2
__device__ __align__(16) unsigned g_Hp[MEM * HPAIR];              // fp16 pairs
__device__ __align__(16) unsigned g_Wp[HID * WPAIR];              // fp16 pairs
__device__ __align__(16) unsigned g_xp[(size_t)BATCH * T * XPAIR];
__device__ __align__(16) unsigned g_mp[(size_t)BATCH * T * MPAIR];

// ---------------- helpers ----------------
__device__ __forceinline__ unsigned packh2(float a, float b) {
    __half2 t = __floats2half2_rn(a, b);
    return *reinterpret_cast<unsigned*>(&t);
}
__device__ __forceinline__ uint32_t smem_u32(const void* p) {
    uint32_t a;
    asm("{ .reg .u64 t; cvta.to.shared.u64 t, %1; cvt.u32.u64 %0, t; }" : "=r"(a) : "l"(p));
    return a;
}
__device__ __forceinline__ void cp16(uint32_t saddr, const void* g) {
    asm volatile("cp.async.cg.shared.global [%0], [%1], 16;" :: "r"(saddr), "l"(g));
}
__device__ __forceinline__ void cp_commit() {
    asm volatile("cp.async.commit_group;" ::: "memory");
}
__device__ __forceinline__ void cp_wait1() {
    asm volatile("cp.async.wait_group 1;" ::: "memory");
}
// ldmatrix x4: 4 8x8 b16 fragments; per-lane row addresses
__device__ __forceinline__ void ldsm4(unsigned& r0, unsigned& r1,
                                      unsigned& r2, unsigned& r3, uint32_t a) {
    asm volatile("ldmatrix.sync.aligned.m8n8.x4.shared.b16 {%0,%1,%2,%3}, [%4];"
                 : "=r"(r0), "=r"(r1), "=r"(r2), "=r"(r3) : "r"(a));
}
// D += A(16x16) * B(16x8), fp16 in, fp32 accum
__device__ __forceinline__ void mma16816(float* c, const unsigned* a,
                                         unsigned b0, unsigned b1) {
    asm volatile(
        "mma.sync.aligned.m16n8k16.row.col.f32.f16.f16.f32 "
        "{%0,%1,%2,%3},{%4,%5,%6,%7},{%8,%9},{%0,%1,%2,%3};"
        : "+f"(c[0]), "+f"(c[1]), "+f"(c[2]), "+f"(c[3])
        : "r"(a[0]), "r"(a[1]), "r"(a[2]), "r"(a[3]), "r"(b0), "r"(b1));
}

// ---------------------------------------------------------------------------
// Front kernel: CTAs [0, UX_BLOCKS) compute u=relu(x@Wu) and pack x -> fp16;
// CTAs [UX_BLOCKS, ...) pack H and W_h -> fp16 pairs.
// ---------------------------------------------------------------------------
__global__ __launch_bounds__(256) void k_front(const float* __restrict__ x,
                                               const float* __restrict__ Wu,
                                               const float* __restrict__ Wh,
                                               const float* __restrict__ H) {
    int bx = blockIdx.x;
    if (bx < UX_BLOCKS) {
        __shared__ float w[IN_DIM];
        int tid = threadIdx.x;
        w[tid] = Wu[tid];
        __syncthreads();
        int warp = tid >> 5, lane = tid & 31;
        int row = bx * 8 + warp;
        const float* xr = x + (size_t)row * IN_DIM;
        float4 a = *(const float4*)(xr + lane * 4);
        float4 b = *(const float4*)(xr + 128 + lane * 4);
        {
            uint2 pa = make_uint2(packh2(a.x, a.y), packh2(a.z, a.w));
            uint2 pb = make_uint2(packh2(b.x, b.y), packh2(b.z, b.w));
            *(uint2*)&g_xp[(size_t)row * XPAIR + 2 * lane]      = pa;
            *(uint2*)&g_xp[(size_t)row * XPAIR + 64 + 2 * lane] = pb;
        }
        int j0 = lane * 4;
        float s = a.x * w[j0] + a.y * w[j0 + 1] + a.z * w[j0 + 2] + a.w * w[j0 + 3]
                + b.x * w[128 + j0] + b.y * w[128 + j0 + 1]
                + b.z * w[128 + j0 + 2] + b.w * w[128 + j0 + 3];
#pragma unroll
        for (int off = 16; off; off >>= 1) s += __shfl_xor_sync(0xffffffffu, s, off);
        if (lane == 0) {
            int bb = row >> 12, t = row & (T - 1);
            g_u[bb * USTRIDE + S + t] = fmaxf(s, 0.0f);
        }
    } else {
        size_t i = (size_t)(bx - UX_BLOCKS) * 256 + threadIdx.x;
        if (i < HTOT) {
            g_Hp[i] = packh2(H[2 * i], H[2 * i + 1]);
        } else if (i < HTOT + WTOT) {
            size_t p = i - HTOT;
            g_Wp[p] = packh2(Wh[2 * p], Wh[2 * p + 1]);
        }
    }
}

// reversed pairs: up[y] = (u[y], u[y-1]) as fp16x2, pads produce exact zeros
__global__ void k_pack_u() {
    int y = blockIdx.x * 256 + threadIdx.x;
    if (y >= BATCH * USTRIDE) return;
    int local = y % USTRIDE;
    float v0 = 0.0f, v1 = 0.0f;
    if (local >= S) v0 = g_u[y];
    if (local > S)  v1 = g_u[y - 1];
    g_up[y] = packh2(v0, v1);
}

// ---------------------------------------------------------------------------
// Conv: m tile 128 tau x 128 k, pure fp16 single-term HMMA.
// B fragments via ldmatrix.x4; A (Toeplitz) via scalar LDS + diag sharing.
// LPT CTA order; i==0 triangular skip; 3-stage cp.async pipeline.
// Stage layout (words): H 8704 | u 256  = 8960
// ---------------------------------------------------------------------------
#define CV_STG 8960
#define CV_SMEM_BYTES (3 * CV_STG * 4)   // 107520

__global__ __launch_bounds__(256, 2) void k_conv_hmma() {
    extern __shared__ unsigned sm[];
    uint32_t sb = smem_u32(sm);

    int tid = threadIdx.x, lane = tid & 31, wid = tid >> 5;
    int g = lane >> 2, tig = lane & 3;
    int wm = wid & 3, wn = wid >> 2;

    // LPT: heaviest tiles (jb=31) occupy the first 64 bids, etc.
    int bid = blockIdx.x + 32 * (blockIdx.y + 2 * blockIdx.z);
    int jb = NB - 1 - (bid >> 6);
    int idx = bid & 63;
    int ks = idx & 1, b = idx >> 1;

    float acc[2][8][4];
#pragma unroll
    for (int mt = 0; mt < 2; ++mt)
#pragma unroll
        for (int nt = 0; nt < 8; ++nt)
#pragma unroll
            for (int q = 0; q < 4; ++q) acc[mt][nt][q] = 0.0f;

    const int srow = tid >> 1, shalf = tid & 1;
    const size_t hrow = (size_t)(ks * 128 + srow) * HPAIR + shalf * 32;

    // ldmatrix per-lane offset into H tile (stride 68 words):
    // grp0: b0(np even rows), grp1: +16B (k hi), grp2: rows+8, grp3: rows+8 +16B
    const uint32_t bOff = (uint32_t)((wn * 64 + ((lane >> 4) << 3) + (lane & 7)) * 68) * 4
                        + ((lane & 8) << 1);

    auto stage = [&](int i, int s) {
        if (i <= jb) {
            int l = jb - i;
            const unsigned* shh = &g_Hp[hrow + l * 64];
            uint32_t dh = sb + (uint32_t)(s * CV_STG + srow * 68 + shalf * 32) * 4;
#pragma unroll
            for (int q = 0; q < 8; ++q) cp16(dh + q * 16, shh + q * 4);
            int Wb = b * USTRIDE + i * S;    // window start; front pad covers t<0
            if (tid < 64)
                cp16(sb + (uint32_t)(s * CV_STG + 8704 + tid * 4) * 4,
                     &g_up[Wb + tid * 4]);
        }
        cp_commit();
    };

    stage(0, 0);
    stage(1, 1);
    int p = 0;
    for (int i = 0; i <= jb; ++i) {
        cp_wait1();
        __syncthreads();
        int s2 = p + 2; if (s2 >= 3) s2 -= 3;
        stage(i + 2, s2);

        unsigned* uw = sm + p * CV_STG + 8704;
        uint32_t bBase = sb + (uint32_t)(p * CV_STG) * 4 + bOff;

#pragma unroll
        for (int kk = 0; kk < 8; ++kk) {
            bool sk0 = (i == 0) && (kk > 2 * wm);
            bool sk1 = (i == 0) && (kk > 2 * wm + 1);
            unsigned ah[2][4];
#pragma unroll
            for (int mt = 0; mt < 2; ++mt) {
                bool sk = mt ? sk1 : sk0;
                if (!sk) {
                    int base = 128 + wm * 32 + mt * 16 + g - kk * 16 - 2 * tig;
                    ah[mt][0] = uw[base];
                    ah[mt][1] = uw[base + 8];
                    ah[mt][2] = uw[base - 8];
                    ah[mt][3] = ah[mt][0];   // Toeplitz diagonal
                }
            }
#pragma unroll
            for (int np = 0; np < 4; ++np) {     // nt pairs: nt = 2np, 2np+1
                unsigned rb[4];
                ldsm4(rb[0], rb[1], rb[2], rb[3], bBase + np * (16 * 68 * 4) + kk * 32);
                if (!sk0) {
                    mma16816(acc[0][2 * np],     ah[0], rb[0], rb[1]);
                    mma16816(acc[0][2 * np + 1], ah[0], rb[2], rb[3]);
                }
                if (!sk1) {
                    mma16816(acc[1][2 * np],     ah[1], rb[0], rb[1]);
                    mma16816(acc[1][2 * np + 1], ah[1], rb[2], rb[3]);
                }
            }
        }
        if (++p == 3) p = 0;
    }

    // epilogue: m -> fp16 pairs for gemm2
#pragma unroll
    for (int mt = 0; mt < 2; ++mt) {
        size_t row0 = (size_t)b * T + (size_t)jb * S + wm * 32 + mt * 16 + g;
#pragma unroll
        for (int nt = 0; nt < 8; ++nt) {
            int pp = ks * 64 + wn * 32 + nt * 4 + tig;
            g_mp[row0 * MPAIR + pp]       = packh2(acc[mt][nt][0], acc[mt][nt][1]);
            g_mp[(row0 + 8) * MPAIR + pp] = packh2(acc[mt][nt][2], acc[mt][nt][3]);
        }
    }
}

// ---------------------------------------------------------------------------
// GEMM2: h = relu([m|x] @ W_h^T). CTA = 128 rows x 128 outs, 8 K-chunks of 64.
// A and B fragments via ldmatrix.x4. 3-stage pipeline, one sync per iter.
// Stage (words): As 4608 | Ws 4608
// ---------------------------------------------------------------------------
#define G2_AS 4608
#define G2_STG (2 * G2_AS)               // 9216 words
#define G2_SMEM_BYTES (3 * G2_STG * 4)   // 110592

__global__ __launch_bounds__(256, 2) void k_gemm2_hmma(float* __restrict__ out) {
    extern __shared__ unsigned sm[];
    uint32_t sb = smem_u32(sm);

    int tid = threadIdx.x, lane = tid & 31, wid = tid >> 5;
    int g = lane >> 2, tig = lane & 3;
    int wm = wid & 3, wn = wid >> 2;
    int ob = blockIdx.x, tb = blockIdx.y;

    float acc[2][8][4];
#pragma unroll
    for (int mt = 0; mt < 2; ++mt)
#pragma unroll
        for (int nt = 0; nt < 8; ++nt)
#pragma unroll
            for (int q = 0; q < 4; ++q) acc[mt][nt][q] = 0.0f;

    const int srow = tid >> 1, shalf = tid & 1;
    const size_t arow0 = ((size_t)tb * 128 + srow) * 128 + shalf * 16;
    const size_t wrow0 = (size_t)(ob * 128 + srow) * WPAIR + shalf * 16;

    // ldmatrix per-lane offsets (stride 36 words):
    // A: grp0=a0(rows), grp1=a1(rows+8), grp2=a2(+16B), grp3=a3(rows+8,+16B)
    const uint32_t aOff = (uint32_t)((wm * 32 + ((lane & 8) ? 8 : 0) + (lane & 7)) * 36) * 4
                        + ((lane & 16) ? 16 : 0);
    // B: grp0=b0(nt even), grp1=b1(+16B), grp2=b0(nt odd, rows+8), grp3=b1(rows+8,+16B)
    const uint32_t bOff = (uint32_t)((wn * 64 + ((lane >> 4) << 3) + (lane & 7)) * 36) * 4
                        + ((lane & 8) << 1);

    auto stage = [&](int c, int s) {
        if (c < 8) {
            const unsigned* pa = (c < 4) ? &g_mp[arow0 + c * 32]
                                         : &g_xp[arow0 + (c - 4) * 32];
            const unsigned* pw = &g_Wp[wrow0 + c * 32];
            uint32_t d0 = sb + (uint32_t)(s * G2_STG + srow * 36 + shalf * 16) * 4;
#pragma unroll
            for (int q = 0; q < 4; ++q) {
                cp16(d0 + q * 16,             pa + q * 4);
                cp16(d0 + G2_AS * 4 + q * 16, pw + q * 4);
            }
        }
        cp_commit();
    };

    stage(0, 0);
    stage(1, 1);
    int p = 0;
    for (int c = 0; c < 8; ++c) {
        cp_wait1();
        __syncthreads();
        int s2 = p + 2; if (s2 >= 3) s2 -= 3;
        stage(c + 2, s2);

        uint32_t aBase = sb + (uint32_t)(p * G2_STG) * 4 + aOff;
        uint32_t bBase = sb + (uint32_t)(p * G2_STG + G2_AS) * 4 + bOff;

#pragma unroll
        for (int kk = 0; kk < 4; ++kk) {
            unsigned ah[2][4];
#pragma unroll
            for (int mt = 0; mt < 2; ++mt)
                ldsm4(ah[mt][0], ah[mt][1], ah[mt][2], ah[mt][3],
                      aBase + mt * (16 * 36 * 4) + kk * 32);
#pragma unroll
            for (int np = 0; np < 4; ++np) {
                unsigned rb[4];
                ldsm4(rb[0], rb[1], rb[2], rb[3], bBase + np * (16 * 36 * 4) + kk * 32);
                mma16816(acc[0][2 * np],     ah[0], rb[0], rb[1]);
                mma16816(acc[0][2 * np + 1], ah[0], rb[2], rb[3]);
                mma16816(acc[1][2 * np],     ah[1], rb[0], rb[1]);
                mma16816(acc[1][2 * np + 1], ah[1], rb[2], rb[3]);
            }
        }
        if (++p == 3) p = 0;
    }

    // epilogue: relu, write h and h_n
    const size_t HSIZE = (size_t)BATCH * T * HID;
#pragma unroll
    for (int mt = 0; mt < 2; ++mt) {
        size_t row0 = (size_t)tb * 128 + wm * 32 + mt * 16 + g;
#pragma unroll
        for (int nt = 0; nt < 8; ++nt) {
            int col = ob * 128 + wn * 64 + nt * 8 + tig * 2;
            float2 v0 = make_float2(fmaxf(acc[mt][nt][0], 0.f), fmaxf(acc[mt][nt][1], 0.f));
            float2 v1 = make_float2(fmaxf(acc[mt][nt][2], 0.f), fmaxf(acc[mt][nt][3], 0.f));
            *(float2*)&out[row0 * HID + col] = v0;
            *(float2*)&out[(row0 + 8) * HID + col] = v1;
            if ((row0 & (size_t)(T - 1)) == (size_t)(T - 1))
                *(float2*)&out[HSIZE + (row0 >> 12) * HID + col] = v0;
            if (((row0 + 8) & (size_t)(T - 1)) == (size_t)(T - 1))
                *(float2*)&out[HSIZE + ((row0 + 8) >> 12) * HID + col] = v1;
        }
    }
}

// ---------------------------------------------------------------------------
extern "C" void kernel_launch(void* const* d_in, const int* in_sizes, int n_in,
                              void* d_out, int out_size) {
    const float* x  = (const float*)d_in[0];   // (32, 4096, 256)
    const float* Wu = (const float*)d_in[1];   // (1, 256)
    const float* Wh = (const float*)d_in[2];   // (512, 512)
    const float* H  = (const float*)d_in[3];   // (256, 4096)
    float* out = (float*)d_out;

    (void)in_sizes; (void)n_in; (void)out_size;

    static int smem_set = 0;
    if (!smem_set) {
        cudaFuncSetAttribute(k_conv_hmma, cudaFuncAttributeMaxDynamicSharedMemorySize,
                             CV_SMEM_BYTES);
        cudaFuncSetAttribute(k_gemm2_hmma, cudaFuncAttributeMaxDynamicSharedMemorySize,
                             G2_SMEM_BYTES);
        smem_set = 1;
    }

    k_front<<<UX_BLOCKS + PREP_BLOCKS, 256>>>(x, Wu, Wh, H);
    k_pack_u<<<(BATCH * USTRIDE + 255) / 256, 256>>>();
    k_conv_hmma<<<dim3(NB, 2, BATCH), 256, CV_SMEM_BYTES>>>();
    k_gemm2_hmma<<<dim3(HID / 128, BATCH * T / 128), 256, G2_SMEM_BYTES>>>(out);
}